// round 1
// baseline (speedup 1.0000x reference)
#include <cuda_runtime.h>
#include <cuda_bf16.h>
#include <cstdint>

// Problem constants
#define BATCH   8
#define NPTS    4096
#define CIN_PTS 64
#define NPOINT  1024
#define NCENT   (BATCH * NPOINT)   // 8192
#define FEAT_W  320                // 64 + 128 + 128

// ---------------- device scratch (no allocations allowed) ----------------
__device__ int   g_fps_idx[NCENT];
__device__ float g_new_xyz[NCENT * 3];
__device__ int   g_idx0[NCENT * 16];
__device__ int   g_idx1[NCENT * 32];
__device__ int   g_idx2[NCENT * 128];

// =====================================================================
// Kernel 1: Farthest Point Sampling. One block per batch, 1024 threads.
// Matches JAX: dists init 1e10, farthest init 0, record-then-update,
// argmax with first-index tie-break.
// =====================================================================
__global__ __launch_bounds__(1024) void fps_kernel(const float* __restrict__ xyz,
                                                   float* __restrict__ out_newxyz)
{
    int b = blockIdx.x;
    extern __shared__ float sm[];
    float* sx = sm;
    float* sy = sm + NPTS;
    float* sz = sm + 2 * NPTS;
    float* sd = sm + 3 * NPTS;
    __shared__ float swv[32];
    __shared__ int   swi[32];
    __shared__ int   s_far;

    const float* base = xyz + (size_t)b * NPTS * 3;
    for (int p = threadIdx.x; p < NPTS; p += 1024) {
        sx[p] = base[p * 3 + 0];
        sy[p] = base[p * 3 + 1];
        sz[p] = base[p * 3 + 2];
        sd[p] = 1e10f;
    }
    if (threadIdx.x == 0) s_far = 0;
    __syncthreads();

    int lane = threadIdx.x & 31;
    int wid  = threadIdx.x >> 5;

    for (int it = 0; it < NPOINT; it++) {
        int far = s_far;
        if (threadIdx.x == 0) {
            g_fps_idx[b * NPOINT + it] = far;
            float fx = sx[far], fy = sy[far], fz = sz[far];
            int row = b * NPOINT + it;
            out_newxyz[row * 3 + 0] = fx;
            out_newxyz[row * 3 + 1] = fy;
            out_newxyz[row * 3 + 2] = fz;
            g_new_xyz[row * 3 + 0] = fx;
            g_new_xyz[row * 3 + 1] = fy;
            g_new_xyz[row * 3 + 2] = fz;
        }
        float cx = sx[far], cy = sy[far], cz = sz[far];

        float bv = -1.0f;
        int   bi = 0;
        #pragma unroll
        for (int r = 0; r < 4; r++) {
            int p = threadIdx.x + r * 1024;
            float dx = sx[p] - cx;
            float dy = sy[p] - cy;
            float dz = sz[p] - cz;
            // avoid FMA contraction so selection matches XLA
            float d = __fadd_rn(__fadd_rn(__fmul_rn(dx, dx), __fmul_rn(dy, dy)),
                                __fmul_rn(dz, dz));
            float nd = fminf(sd[p], d);
            sd[p] = nd;
            if (nd > bv) { bv = nd; bi = p; }
        }
        // warp reduce (max value, smallest index on tie)
        #pragma unroll
        for (int off = 16; off >= 1; off >>= 1) {
            float ov = __shfl_down_sync(0xffffffffu, bv, off);
            int   oi = __shfl_down_sync(0xffffffffu, bi, off);
            if (ov > bv || (ov == bv && oi < bi)) { bv = ov; bi = oi; }
        }
        if (lane == 0) { swv[wid] = bv; swi[wid] = bi; }
        __syncthreads();
        if (wid == 0) {
            float v = swv[lane];
            int   i = swi[lane];
            #pragma unroll
            for (int off = 16; off >= 1; off >>= 1) {
                float ov = __shfl_down_sync(0xffffffffu, v, off);
                int   oi = __shfl_down_sync(0xffffffffu, i, off);
                if (ov > v || (ov == v && oi < i)) { v = ov; i = oi; }
            }
            if (lane == 0) s_far = i;
        }
        __syncthreads();
    }
}

// =====================================================================
// Kernel 2: Ball query. One warp per center. Ordered compaction over
// point index (equivalent to the reference's sort trick).
// =====================================================================
__global__ void ballquery_kernel(const float* __restrict__ xyz,
                                 int nsample, float r2,
                                 int* __restrict__ idxout)
{
    int gw = (blockIdx.x * blockDim.x + threadIdx.x) >> 5;
    if (gw >= NCENT) return;
    int lane = threadIdx.x & 31;
    int b = gw >> 10;

    float cx = g_new_xyz[gw * 3 + 0];
    float cy = g_new_xyz[gw * 3 + 1];
    float cz = g_new_xyz[gw * 3 + 2];
    const float* base = xyz + (size_t)b * NPTS * 3;
    int* op = idxout + (size_t)gw * nsample;

    int cnt = 0;
    int first = -1;
    for (int c0 = 0; c0 < NPTS; c0 += 32) {
        int p = c0 + lane;
        float dx = base[p * 3 + 0] - cx;
        float dy = base[p * 3 + 1] - cy;
        float dz = base[p * 3 + 2] - cz;
        float d2 = __fadd_rn(__fadd_rn(__fmul_rn(dx, dx), __fmul_rn(dy, dy)),
                             __fmul_rn(dz, dz));
        bool hit = d2 < r2;
        unsigned m = __ballot_sync(0xffffffffu, hit);
        if (m) {
            if (first < 0) first = c0 + (__ffs(m) - 1);
            if (hit) {
                int pos = cnt + __popc(m & ((1u << lane) - 1u));
                if (pos < nsample) op[pos] = p;
            }
            cnt += __popc(m);
            if (cnt >= nsample) break;
        }
    }
    // pad with first index (always exists: center itself is within radius)
    for (int pos = cnt + lane; pos < nsample; pos += 32) op[pos] = first;
}

// =====================================================================
// Kernel 3: grouped MLP (3 layers, relu) + maxpool. One block per center.
// Register-tiled TS x TO per thread, weights in shared.
// =====================================================================
__host__ __device__ constexpr int cmax3(int a, int b, int c) {
    return a > b ? (a > c ? a : c) : (b > c ? b : c);
}

template<int NS, int Cin, int Cout, int TS, int TO>
__device__ __forceinline__ void dense_layer(const float* __restrict__ in, int inStride,
                                            const float* __restrict__ gW,
                                            const float* __restrict__ gB,
                                            float* __restrict__ out, int outStride,
                                            float* __restrict__ sW)
{
    for (int t = threadIdx.x; t < Cin * Cout; t += 256) sW[t] = gW[t];
    __syncthreads();

    constexpr int TILES_O = Cout / TO;
    constexpr int TILES_S = NS / TS;
    for (int t = threadIdx.x; t < TILES_O * TILES_S; t += 256) {
        int to = t % TILES_O;
        int ts = t / TILES_O;
        int s0 = ts * TS, o0 = to * TO;
        float acc[TS][TO];
        #pragma unroll
        for (int i = 0; i < TS; i++)
            #pragma unroll
            for (int j = 0; j < TO; j++) acc[i][j] = gB[o0 + j];

        for (int k = 0; k < Cin; k++) {
            float wv[TO];
            #pragma unroll
            for (int j = 0; j < TO; j += 4) {
                float4 w4 = *reinterpret_cast<const float4*>(&sW[k * Cout + o0 + j]);
                wv[j] = w4.x; wv[j + 1] = w4.y; wv[j + 2] = w4.z; wv[j + 3] = w4.w;
            }
            float iv[TS];
            #pragma unroll
            for (int i = 0; i < TS; i++) iv[i] = in[(s0 + i) * inStride + k];
            #pragma unroll
            for (int i = 0; i < TS; i++)
                #pragma unroll
                for (int j = 0; j < TO; j++)
                    acc[i][j] = fmaf(iv[i], wv[j], acc[i][j]);
        }
        #pragma unroll
        for (int i = 0; i < TS; i++)
            #pragma unroll
            for (int j = 0; j < TO; j++)
                out[(s0 + i) * outStride + o0 + j] = fmaxf(acc[i][j], 0.0f);
    }
    __syncthreads();
}

template<int NS, int C1, int C2, int C3, int TS, int TO>
__global__ __launch_bounds__(256) void mlp_kernel(const float* __restrict__ xyz,
                                                  const float* __restrict__ points,
                                                  const int* __restrict__ idxbuf,
                                                  const float* __restrict__ W1, const float* __restrict__ B1,
                                                  const float* __restrict__ W2, const float* __restrict__ B2,
                                                  const float* __restrict__ W3, const float* __restrict__ B3,
                                                  float* __restrict__ outF, int featOff)
{
    constexpr int CA   = (C1 > C3 ? C1 : C3);
    constexpr int WMAX = cmax3(67 * C1, C1 * C2, C2 * C3);
    constexpr int INS  = 68; // padded input stride (67 used)

    extern __shared__ float sm[];
    float* sIn  = sm;                       // NS * 68
    float* bufA = sIn + NS * INS;           // NS * CA
    float* bufB = bufA + NS * CA;           // NS * C2
    float* sW   = bufB + NS * C2;           // WMAX
    int*   sIdx = (int*)(sW + WMAX);        // NS

    int gid = blockIdx.x;
    int b   = gid >> 10;
    int cen = gid & 1023;

    for (int t = threadIdx.x; t < NS; t += 256) sIdx[t] = idxbuf[(size_t)gid * NS + t];
    __syncthreads();

    // gather point features
    const float* pB = points + (size_t)b * NPTS * CIN_PTS;
    for (int t = threadIdx.x; t < NS * CIN_PTS; t += 256) {
        int s = t >> 6, k = t & 63;
        sIn[s * INS + k] = pB[(size_t)sIdx[s] * CIN_PTS + k];
    }
    // gather xyz diff
    float cx = g_new_xyz[gid * 3 + 0];
    float cy = g_new_xyz[gid * 3 + 1];
    float cz = g_new_xyz[gid * 3 + 2];
    const float* xB = xyz + (size_t)b * NPTS * 3;
    for (int t = threadIdx.x; t < NS * 3; t += 256) {
        int s = t / 3, c = t - s * 3;
        float cc = (c == 0) ? cx : ((c == 1) ? cy : cz);
        sIn[s * INS + 64 + c] = xB[(size_t)sIdx[s] * 3 + c] - cc;
    }
    __syncthreads();

    dense_layer<NS, 67, C1, TS, TO>(sIn, INS, W1, B1, bufA, CA, sW);
    dense_layer<NS, C1, C2, TS, TO>(bufA, CA, W2, B2, bufB, C2, sW);
    dense_layer<NS, C2, C3, TS, TO>(bufB, C2, W3, B3, bufA, CA, sW);

    // maxpool over samples -> output
    for (int o = threadIdx.x; o < C3; o += 256) {
        float m = bufA[o];
        #pragma unroll 4
        for (int s = 1; s < NS; s++) m = fmaxf(m, bufA[s * CA + o]);
        outF[(size_t)gid * FEAT_W + featOff + o] = m;
    }
}

// =====================================================================
// host launch
// =====================================================================
extern "C" void kernel_launch(void* const* d_in, const int* in_sizes, int n_in,
                              void* d_out, int out_size)
{
    const float* xyz = (const float*)d_in[0];
    const float* pts = (const float*)d_in[1];
    const float* W[3][3];
    const float* Bv[3][3];
    int k = 2;
    for (int bi = 0; bi < 3; bi++)
        for (int li = 0; li < 3; li++) {
            W[bi][li]  = (const float*)d_in[k++];
            Bv[bi][li] = (const float*)d_in[k++];
        }

    float* out       = (float*)d_out;
    float* out_newxyz = out;
    float* out_feat   = out + (size_t)NCENT * 3;

    // smem sizes
    const int fps_smem = 4 * NPTS * 4; // 64 KB
    auto smemFor = [](int NS, int C1, int C2, int C3) {
        int CA = (C1 > C3 ? C1 : C3);
        int WM = cmax3(67 * C1, C1 * C2, C2 * C3);
        return (NS * 68 + NS * CA + NS * C2 + WM) * 4 + NS * 4;
    };
    const int sm0 = smemFor(16, 32, 32, 64);
    const int sm1 = smemFor(32, 64, 64, 128);
    const int sm2 = smemFor(128, 64, 96, 128);

    cudaFuncSetAttribute(fps_kernel, cudaFuncAttributeMaxDynamicSharedMemorySize, fps_smem);
    cudaFuncSetAttribute((const void*)mlp_kernel<16, 32, 32, 64, 2, 8>,
                         cudaFuncAttributeMaxDynamicSharedMemorySize, sm0);
    cudaFuncSetAttribute((const void*)mlp_kernel<32, 64, 64, 128, 4, 8>,
                         cudaFuncAttributeMaxDynamicSharedMemorySize, sm1);
    cudaFuncSetAttribute((const void*)mlp_kernel<128, 64, 96, 128, 8, 8>,
                         cudaFuncAttributeMaxDynamicSharedMemorySize, sm2);

    // 1) FPS (also writes new_xyz to output + scratch)
    fps_kernel<<<BATCH, 1024, fps_smem>>>(xyz, out_newxyz);

    // 2) ball queries (r^2 computed in double, cast to float, matching XLA)
    const float r2_0 = (float)(0.1 * 0.1);
    const float r2_1 = (float)(0.2 * 0.2);
    const float r2_2 = (float)(0.4 * 0.4);
    int bq_blocks = NCENT / 8; // 8 warps per 256-thread block
    ballquery_kernel<<<bq_blocks, 256>>>(xyz, 16,  r2_0, g_idx0);
    ballquery_kernel<<<bq_blocks, 256>>>(xyz, 32,  r2_1, g_idx1);
    ballquery_kernel<<<bq_blocks, 256>>>(xyz, 128, r2_2, g_idx2);

    // 3) grouped MLPs + maxpool
    mlp_kernel<16, 32, 32, 64, 2, 8><<<NCENT, 256, sm0>>>(
        xyz, pts, g_idx0,
        W[0][0], Bv[0][0], W[0][1], Bv[0][1], W[0][2], Bv[0][2],
        out_feat, 0);
    mlp_kernel<32, 64, 64, 128, 4, 8><<<NCENT, 256, sm1>>>(
        xyz, pts, g_idx1,
        W[1][0], Bv[1][0], W[1][1], Bv[1][1], W[1][2], Bv[1][2],
        out_feat, 64);
    mlp_kernel<128, 64, 96, 128, 8, 8><<<NCENT, 256, sm2>>>(
        xyz, pts, g_idx2,
        W[2][0], Bv[2][0], W[2][1], Bv[2][1], W[2][2], Bv[2][2],
        out_feat, 192);
}

// round 2
// speedup vs baseline: 1.2999x; 1.2999x over previous
#include <cuda_runtime.h>
#include <cuda_bf16.h>
#include <cstdint>

// Problem constants
#define BATCH   8
#define NPTS    4096
#define CIN_PTS 64
#define NPOINT  1024
#define NCENT   (BATCH * NPOINT)   // 8192
#define FEAT_W  320                // 64 + 128 + 128

// ---------------- device scratch (no allocations allowed) ----------------
__device__ float g_new_xyz[NCENT * 3];
__device__ int   g_idx0[NCENT * 16];
__device__ int   g_idx1[NCENT * 32];
__device__ int   g_idx2[NCENT * 128];

// =====================================================================
// Kernel 1: Farthest Point Sampling. One block per batch, 1024 threads.
// Register-resident running distances, one barrier per iteration,
// rotating 3-slot 64-bit shared atomicMax key (value||(~index)) which
// reproduces JAX argmax first-index tie-break exactly.
// =====================================================================
__global__ __launch_bounds__(1024) void fps_kernel(const float* __restrict__ xyz,
                                                   float* __restrict__ out_newxyz)
{
    int b = blockIdx.x;
    extern __shared__ float sm[];
    float* sx = sm;
    float* sy = sm + NPTS;
    float* sz = sm + 2 * NPTS;
    __shared__ unsigned long long skey[3];

    const float* base = xyz + (size_t)b * NPTS * 3;
    float px[4], py[4], pz[4], pd[4];
    #pragma unroll
    for (int r = 0; r < 4; r++) {
        int p = threadIdx.x + r * 1024;
        float x = base[p * 3 + 0];
        float y = base[p * 3 + 1];
        float z = base[p * 3 + 2];
        sx[p] = x; sy[p] = y; sz[p] = z;
        px[r] = x; py[r] = y; pz[r] = z;
        pd[r] = 1e10f;
    }
    if (threadIdx.x == 0) {
        skey[0] = 0xFFFFFFFFull;  // decodes to index 0
        skey[1] = 0ull;
        skey[2] = 0ull;
    }
    __syncthreads();

    int lane = threadIdx.x & 31;

    for (int it = 0; it < NPOINT; it++) {
        int cur = it % 3, nxt = (it + 1) % 3, rst = (it + 2) % 3;
        unsigned int low = (unsigned int)skey[cur];
        int far = (int)(0xFFFFFFFFu - low);

        if (threadIdx.x == 0) {
            float fx = sx[far], fy = sy[far], fz = sz[far];
            int row = b * NPOINT + it;
            out_newxyz[row * 3 + 0] = fx;
            out_newxyz[row * 3 + 1] = fy;
            out_newxyz[row * 3 + 2] = fz;
            g_new_xyz[row * 3 + 0] = fx;
            g_new_xyz[row * 3 + 1] = fy;
            g_new_xyz[row * 3 + 2] = fz;
            skey[rst] = 0ull;
        }
        float cx = sx[far], cy = sy[far], cz = sz[far];

        float bv = -1.0f;
        int   bi = 0;
        #pragma unroll
        for (int r = 0; r < 4; r++) {
            float dx = px[r] - cx;
            float dy = py[r] - cy;
            float dz = pz[r] - cz;
            float d = __fadd_rn(__fadd_rn(__fmul_rn(dx, dx), __fmul_rn(dy, dy)),
                                __fmul_rn(dz, dz));
            float nd = fminf(pd[r], d);
            pd[r] = nd;
            if (nd > bv) { bv = nd; bi = threadIdx.x + r * 1024; }
        }
        #pragma unroll
        for (int off = 16; off >= 1; off >>= 1) {
            float ov = __shfl_down_sync(0xffffffffu, bv, off);
            int   oi = __shfl_down_sync(0xffffffffu, bi, off);
            if (ov > bv || (ov == bv && oi < bi)) { bv = ov; bi = oi; }
        }
        if (lane == 0) {
            unsigned long long key =
                ((unsigned long long)__float_as_uint(bv) << 32) |
                (unsigned long long)(0xFFFFFFFFu - (unsigned int)bi);
            atomicMax(&skey[nxt], key);
        }
        __syncthreads();
    }
}

// =====================================================================
// Kernel 2: fused ball query (all three radii in one smem-staged scan).
// One warp per center; ordered compaction == reference sort trick.
// =====================================================================
__global__ __launch_bounds__(256) void bq_fused_kernel(const float* __restrict__ xyz,
                                                       int* __restrict__ o0,
                                                       int* __restrict__ o1,
                                                       int* __restrict__ o2)
{
    extern __shared__ float sm[];
    float* sx = sm;
    float* sy = sm + NPTS;
    float* sz = sm + 2 * NPTS;

    int wid  = threadIdx.x >> 5;
    int lane = threadIdx.x & 31;
    int gw   = blockIdx.x * 8 + wid;       // center id
    int b    = gw >> 10;

    const float* base = xyz + (size_t)b * NPTS * 3;
    for (int t = threadIdx.x; t < NPTS * 3; t += 256) {
        int p = t / 3, c = t - p * 3;
        float v = base[t];
        (c == 0 ? sx : (c == 1 ? sy : sz))[p] = v;
    }
    __syncthreads();

    const float r2_0 = (float)(0.1 * 0.1);
    const float r2_1 = (float)(0.2 * 0.2);
    const float r2_2 = (float)(0.4 * 0.4);

    float cx = g_new_xyz[gw * 3 + 0];
    float cy = g_new_xyz[gw * 3 + 1];
    float cz = g_new_xyz[gw * 3 + 2];

    int* p0 = o0 + (size_t)gw * 16;
    int* p1 = o1 + (size_t)gw * 32;
    int* p2 = o2 + (size_t)gw * 128;

    int c0 = 0, c1 = 0, c2 = 0;
    int f0 = -1, f1 = -1, f2 = -1;
    unsigned lmask = (1u << lane) - 1u;

    for (int s = 0; s < NPTS; s += 32) {
        int p = s + lane;
        float dx = sx[p] - cx;
        float dy = sy[p] - cy;
        float dz = sz[p] - cz;
        float d2 = __fadd_rn(__fadd_rn(__fmul_rn(dx, dx), __fmul_rn(dy, dy)),
                             __fmul_rn(dz, dz));
        bool h0 = d2 < r2_0, h1 = d2 < r2_1, h2 = d2 < r2_2;
        unsigned m0 = __ballot_sync(0xffffffffu, h0);
        unsigned m1 = __ballot_sync(0xffffffffu, h1);
        unsigned m2 = __ballot_sync(0xffffffffu, h2);
        if (m0) {
            if (f0 < 0) f0 = s + (__ffs(m0) - 1);
            if (h0) { int pos = c0 + __popc(m0 & lmask); if (pos < 16) p0[pos] = p; }
            c0 += __popc(m0);
        }
        if (m1) {
            if (f1 < 0) f1 = s + (__ffs(m1) - 1);
            if (h1) { int pos = c1 + __popc(m1 & lmask); if (pos < 32) p1[pos] = p; }
            c1 += __popc(m1);
        }
        if (m2) {
            if (f2 < 0) f2 = s + (__ffs(m2) - 1);
            if (h2) { int pos = c2 + __popc(m2 & lmask); if (pos < 128) p2[pos] = p; }
            c2 += __popc(m2);
        }
        if (c0 >= 16 && c1 >= 32 && c2 >= 128) break;
    }
    for (int pos = c0 + lane; pos < 16; pos += 32) p0[pos] = f0;
    for (int pos = c1 + lane; pos < 32; pos += 32) p1[pos] = f1;
    for (int pos = c2 + lane; pos < 128; pos += 32) p2[pos] = f2;
}

// =====================================================================
// fp32 grouped MLP (scales 0 and 1) — unchanged from round 1.
// =====================================================================
__host__ __device__ constexpr int cmax3(int a, int b, int c) {
    return a > b ? (a > c ? a : c) : (b > c ? b : c);
}

template<int NS, int Cin, int Cout, int TS, int TO>
__device__ __forceinline__ void dense_layer(const float* __restrict__ in, int inStride,
                                            const float* __restrict__ gW,
                                            const float* __restrict__ gB,
                                            float* __restrict__ out, int outStride,
                                            float* __restrict__ sW)
{
    for (int t = threadIdx.x; t < Cin * Cout; t += 256) sW[t] = gW[t];
    __syncthreads();

    constexpr int TILES_O = Cout / TO;
    constexpr int TILES_S = NS / TS;
    for (int t = threadIdx.x; t < TILES_O * TILES_S; t += 256) {
        int to = t % TILES_O;
        int ts = t / TILES_O;
        int s0 = ts * TS, o0 = to * TO;
        float acc[TS][TO];
        #pragma unroll
        for (int i = 0; i < TS; i++)
            #pragma unroll
            for (int j = 0; j < TO; j++) acc[i][j] = gB[o0 + j];

        for (int k = 0; k < Cin; k++) {
            float wv[TO];
            #pragma unroll
            for (int j = 0; j < TO; j += 4) {
                float4 w4 = *reinterpret_cast<const float4*>(&sW[k * Cout + o0 + j]);
                wv[j] = w4.x; wv[j + 1] = w4.y; wv[j + 2] = w4.z; wv[j + 3] = w4.w;
            }
            float iv[TS];
            #pragma unroll
            for (int i = 0; i < TS; i++) iv[i] = in[(s0 + i) * inStride + k];
            #pragma unroll
            for (int i = 0; i < TS; i++)
                #pragma unroll
                for (int j = 0; j < TO; j++)
                    acc[i][j] = fmaf(iv[i], wv[j], acc[i][j]);
        }
        #pragma unroll
        for (int i = 0; i < TS; i++)
            #pragma unroll
            for (int j = 0; j < TO; j++)
                out[(s0 + i) * outStride + o0 + j] = fmaxf(acc[i][j], 0.0f);
    }
    __syncthreads();
}

template<int NS, int C1, int C2, int C3, int TS, int TO>
__global__ __launch_bounds__(256) void mlp_kernel(const float* __restrict__ xyz,
                                                  const float* __restrict__ points,
                                                  const int* __restrict__ idxbuf,
                                                  const float* __restrict__ W1, const float* __restrict__ B1,
                                                  const float* __restrict__ W2, const float* __restrict__ B2,
                                                  const float* __restrict__ W3, const float* __restrict__ B3,
                                                  float* __restrict__ outF, int featOff)
{
    constexpr int CA   = (C1 > C3 ? C1 : C3);
    constexpr int WMAX = cmax3(67 * C1, C1 * C2, C2 * C3);
    constexpr int INS  = 68;

    extern __shared__ float sm[];
    float* sIn  = sm;
    float* bufA = sIn + NS * INS;
    float* bufB = bufA + NS * CA;
    float* sW   = bufB + NS * C2;
    int*   sIdx = (int*)(sW + WMAX);

    int gid = blockIdx.x;
    int b   = gid >> 10;

    for (int t = threadIdx.x; t < NS; t += 256) sIdx[t] = idxbuf[(size_t)gid * NS + t];
    __syncthreads();

    const float* pB = points + (size_t)b * NPTS * CIN_PTS;
    for (int t = threadIdx.x; t < NS * CIN_PTS; t += 256) {
        int s = t >> 6, k = t & 63;
        sIn[s * INS + k] = pB[(size_t)sIdx[s] * CIN_PTS + k];
    }
    float cx = g_new_xyz[gid * 3 + 0];
    float cy = g_new_xyz[gid * 3 + 1];
    float cz = g_new_xyz[gid * 3 + 2];
    const float* xB = xyz + (size_t)b * NPTS * 3;
    for (int t = threadIdx.x; t < NS * 3; t += 256) {
        int s = t / 3, c = t - s * 3;
        float cc = (c == 0) ? cx : ((c == 1) ? cy : cz);
        sIn[s * INS + 64 + c] = xB[(size_t)sIdx[s] * 3 + c] - cc;
    }
    __syncthreads();

    dense_layer<NS, 67, C1, TS, TO>(sIn, INS, W1, B1, bufA, CA, sW);
    dense_layer<NS, C1, C2, TS, TO>(bufA, CA, W2, B2, bufB, C2, sW);
    dense_layer<NS, C2, C3, TS, TO>(bufB, C2, W3, B3, bufA, CA, sW);

    for (int o = threadIdx.x; o < C3; o += 256) {
        float m = bufA[o];
        #pragma unroll 4
        for (int s = 1; s < NS; s++) m = fmaxf(m, bufA[s * CA + o]);
        outF[(size_t)gid * FEAT_W + featOff + o] = m;
    }
}

// =====================================================================
// Scale-2 MLP: tf32 mma.sync.m16n8k8 tensor-core path.
// Block = one center (M=128 samples), 256 threads = 8 warps (4M x 2N).
// Layer 3 fused with maxpool (warp shuffle + shared atomicMax).
// =====================================================================
__device__ __forceinline__ uint32_t f2tf32(float f) {
    uint32_t r; asm("cvt.rna.tf32.f32 %0, %1;" : "=r"(r) : "f"(f)); return r;
}

__device__ __forceinline__ void mma_tf32(float* d, const uint32_t* a, const uint32_t* b) {
    asm volatile("mma.sync.aligned.m16n8k8.row.col.f32.tf32.tf32.f32 "
                 "{%0,%1,%2,%3},{%4,%5,%6,%7},{%8,%9},{%0,%1,%2,%3};"
                 : "+f"(d[0]), "+f"(d[1]), "+f"(d[2]), "+f"(d[3])
                 : "r"(a[0]), "r"(a[1]), "r"(a[2]), "r"(a[3]),
                   "r"(b[0]), "r"(b[1]));
}

// strides (all ≡ 4 mod 32 except 76 ≡ 12 — both conflict-free for frag loads)
#define S_IN   76    // input stage stride (67 used, cols 67..75 zero)
#define S_B1   68    // layer-1 output stride (64 used)
#define S_B2   100   // layer-2 output stride (96 used)
#define NP_W1  68
#define NP_W2  100
#define NP_W3  132
#define SW_MAX (96 * 132)

// generic mma layer: KSTEPS k-blocks, A[128][SA], W[*][NP], NT 8-wide n-tiles per warp
template<int KSTEPS, int SA, int NP, int NT, int SOUT, bool FINAL>
__device__ __forceinline__ void mma_layer(const float* __restrict__ sA,
                                          const float* __restrict__ sW,
                                          const float* __restrict__ gBias,
                                          float* __restrict__ sOut,
                                          int* __restrict__ sMaxI)
{
    int lane = threadIdx.x & 31;
    int w    = threadIdx.x >> 5;
    int g    = lane >> 2;
    int tg   = lane & 3;
    int m0   = (w >> 1) * 32;
    int n0   = (w & 1) * (NT * 8);

    float acc[2][NT][4];
    #pragma unroll
    for (int mt = 0; mt < 2; mt++)
        #pragma unroll
        for (int nt = 0; nt < NT; nt++)
            #pragma unroll
            for (int i = 0; i < 4; i++) acc[mt][nt][i] = 0.0f;

    for (int ks = 0; ks < KSTEPS; ks++) {
        int k0 = ks * 8;
        uint32_t a[2][4];
        #pragma unroll
        for (int mt = 0; mt < 2; mt++) {
            const float* Ab = sA + (m0 + 16 * mt) * SA + k0;
            a[mt][0] = f2tf32(Ab[g * SA + tg]);
            a[mt][1] = f2tf32(Ab[(g + 8) * SA + tg]);
            a[mt][2] = f2tf32(Ab[g * SA + tg + 4]);
            a[mt][3] = f2tf32(Ab[(g + 8) * SA + tg + 4]);
        }
        #pragma unroll
        for (int nt = 0; nt < NT; nt++) {
            const float* Wb = sW + k0 * NP + n0 + 8 * nt;
            uint32_t bfr[2];
            bfr[0] = f2tf32(Wb[tg * NP + g]);
            bfr[1] = f2tf32(Wb[(tg + 4) * NP + g]);
            mma_tf32(acc[0][nt], a[0], bfr);
            mma_tf32(acc[1][nt], a[1], bfr);
        }
    }

    if (!FINAL) {
        #pragma unroll
        for (int mt = 0; mt < 2; mt++)
            #pragma unroll
            for (int nt = 0; nt < NT; nt++) {
                int row = m0 + 16 * mt + g;
                int col = n0 + 8 * nt + 2 * tg;
                float b0v = gBias[col], b1v = gBias[col + 1];
                sOut[row * SOUT + col]           = fmaxf(acc[mt][nt][0] + b0v, 0.0f);
                sOut[row * SOUT + col + 1]       = fmaxf(acc[mt][nt][1] + b1v, 0.0f);
                sOut[(row + 8) * SOUT + col]     = fmaxf(acc[mt][nt][2] + b0v, 0.0f);
                sOut[(row + 8) * SOUT + col + 1] = fmaxf(acc[mt][nt][3] + b1v, 0.0f);
            }
    } else {
        #pragma unroll
        for (int nt = 0; nt < NT; nt++) {
            int col = n0 + 8 * nt + 2 * tg;
            float b0v = gBias[col], b1v = gBias[col + 1];
            float v0 = fmaxf(fmaxf(acc[0][nt][0], acc[0][nt][2]),
                             fmaxf(acc[1][nt][0], acc[1][nt][2]));
            float v1 = fmaxf(fmaxf(acc[0][nt][1], acc[0][nt][3]),
                             fmaxf(acc[1][nt][1], acc[1][nt][3]));
            v0 = fmaxf(v0 + b0v, 0.0f);
            v1 = fmaxf(v1 + b1v, 0.0f);
            #pragma unroll
            for (int off = 4; off < 32; off <<= 1) {
                v0 = fmaxf(v0, __shfl_xor_sync(0xffffffffu, v0, off));
                v1 = fmaxf(v1, __shfl_xor_sync(0xffffffffu, v1, off));
            }
            if (g == 0) {
                atomicMax(&sMaxI[col],     __float_as_int(v0));
                atomicMax(&sMaxI[col + 1], __float_as_int(v1));
            }
        }
    }
}

template<int ROWS, int KR, int NC, int NP>
__device__ __forceinline__ void stage_w(float* __restrict__ sW, const float* __restrict__ gW)
{
    for (int t = threadIdx.x; t < ROWS * NP; t += 256) {
        int r = t / NP, c = t - r * NP;
        sW[t] = (r < KR && c < NC) ? gW[r * NC + c] : 0.0f;
    }
}

__global__ __launch_bounds__(256) void mlp2_mma_kernel(const float* __restrict__ xyz,
                                                       const float* __restrict__ points,
                                                       const int* __restrict__ idxbuf,
                                                       const float* __restrict__ W1, const float* __restrict__ B1,
                                                       const float* __restrict__ W2, const float* __restrict__ B2,
                                                       const float* __restrict__ W3, const float* __restrict__ B3,
                                                       float* __restrict__ outF)
{
    extern __shared__ float sm[];
    float* sIn  = sm;                         // 128*76
    float* buf1 = sIn + 128 * S_IN;           // 128*68
    float* buf2 = buf1 + 128 * S_B1;          // 128*100
    float* sW   = buf2 + 128 * S_B2;          // 96*132 max
    int*   sMaxI = (int*)(sW + SW_MAX);       // 128
    int*   sIdx  = sMaxI + 128;               // 128

    int gid = blockIdx.x;
    int b   = gid >> 10;

    for (int t = threadIdx.x; t < 128; t += 256) {
        sIdx[t]  = idxbuf[(size_t)gid * 128 + t];
        sMaxI[t] = 0;
    }
    __syncthreads();

    float cx = g_new_xyz[gid * 3 + 0];
    float cy = g_new_xyz[gid * 3 + 1];
    float cz = g_new_xyz[gid * 3 + 2];
    const float* pB = points + (size_t)b * NPTS * CIN_PTS;
    const float* xB = xyz + (size_t)b * NPTS * 3;

    // gather input (points 0..63, xyz-diff 64..66, zero pad 67..75)
    for (int t = threadIdx.x; t < 128 * S_IN; t += 256) {
        int s = t / S_IN, c = t - s * S_IN;
        float v;
        if (c < 64)       v = pB[(size_t)sIdx[s] * CIN_PTS + c];
        else if (c < 67) {
            int d = c - 64;
            float cc = (d == 0) ? cx : ((d == 1) ? cy : cz);
            v = xB[(size_t)sIdx[s] * 3 + d] - cc;
        } else v = 0.0f;
        sIn[t] = v;
    }
    stage_w<72, 67, 64, NP_W1>(sW, W1);
    __syncthreads();

    mma_layer<9, S_IN, NP_W1, 4, S_B1, false>(sIn, sW, B1, buf1, sMaxI);
    __syncthreads();

    stage_w<64, 64, 96, NP_W2>(sW, W2);
    __syncthreads();

    mma_layer<8, S_B1, NP_W2, 6, S_B2, false>(buf1, sW, B2, buf2, sMaxI);
    __syncthreads();

    stage_w<96, 96, 128, NP_W3>(sW, W3);
    __syncthreads();

    mma_layer<12, S_B2, NP_W3, 8, 0, true>(buf2, sW, B3, nullptr, sMaxI);
    __syncthreads();

    for (int t = threadIdx.x; t < 128; t += 256)
        outF[(size_t)gid * FEAT_W + 192 + t] = __int_as_float(sMaxI[t]);
}

// =====================================================================
// host launch
// =====================================================================
extern "C" void kernel_launch(void* const* d_in, const int* in_sizes, int n_in,
                              void* d_out, int out_size)
{
    const float* xyz = (const float*)d_in[0];
    const float* pts = (const float*)d_in[1];
    const float* W[3][3];
    const float* Bv[3][3];
    int k = 2;
    for (int bi = 0; bi < 3; bi++)
        for (int li = 0; li < 3; li++) {
            W[bi][li]  = (const float*)d_in[k++];
            Bv[bi][li] = (const float*)d_in[k++];
        }

    float* out        = (float*)d_out;
    float* out_newxyz = out;
    float* out_feat   = out + (size_t)NCENT * 3;

    const int fps_smem = 3 * NPTS * 4;   // 48 KB
    const int bq_smem  = 3 * NPTS * 4;   // 48 KB
    auto smemFor = [](int NS, int C1, int C2, int C3) {
        int CA = (C1 > C3 ? C1 : C3);
        int WM = cmax3(67 * C1, C1 * C2, C2 * C3);
        return (NS * 68 + NS * CA + NS * C2 + WM) * 4 + NS * 4;
    };
    const int sm0 = smemFor(16, 32, 32, 64);
    const int sm1 = smemFor(32, 64, 64, 128);
    const int sm2 = (128 * S_IN + 128 * S_B1 + 128 * S_B2 + SW_MAX) * 4 + 256 * 4;

    cudaFuncSetAttribute(fps_kernel, cudaFuncAttributeMaxDynamicSharedMemorySize, fps_smem);
    cudaFuncSetAttribute((const void*)mlp_kernel<16, 32, 32, 64, 2, 8>,
                         cudaFuncAttributeMaxDynamicSharedMemorySize, sm0);
    cudaFuncSetAttribute((const void*)mlp_kernel<32, 64, 64, 128, 4, 8>,
                         cudaFuncAttributeMaxDynamicSharedMemorySize, sm1);
    cudaFuncSetAttribute(mlp2_mma_kernel, cudaFuncAttributeMaxDynamicSharedMemorySize, sm2);

    fps_kernel<<<BATCH, 1024, fps_smem>>>(xyz, out_newxyz);

    bq_fused_kernel<<<NCENT / 8, 256, bq_smem>>>(xyz, g_idx0, g_idx1, g_idx2);

    mlp_kernel<16, 32, 32, 64, 2, 8><<<NCENT, 256, sm0>>>(
        xyz, pts, g_idx0,
        W[0][0], Bv[0][0], W[0][1], Bv[0][1], W[0][2], Bv[0][2],
        out_feat, 0);
    mlp_kernel<32, 64, 64, 128, 4, 8><<<NCENT, 256, sm1>>>(
        xyz, pts, g_idx1,
        W[1][0], Bv[1][0], W[1][1], Bv[1][1], W[1][2], Bv[1][2],
        out_feat, 64);
    mlp2_mma_kernel<<<NCENT, 256, sm2>>>(
        xyz, pts, g_idx2,
        W[2][0], Bv[2][0], W[2][1], Bv[2][1], W[2][2], Bv[2][2],
        out_feat);
}

// round 3
// speedup vs baseline: 1.4355x; 1.1043x over previous
#include <cuda_runtime.h>
#include <cuda_bf16.h>
#include <cstdint>

#define BATCH   8
#define NPTS    4096
#define CIN_PTS 64
#define NPOINT  1024
#define NCENT   (BATCH * NPOINT)   // 8192
#define FEAT_W  320

// ---------------- device scratch ----------------
__device__ float g_new_xyz[NCENT * 3];
__device__ int   g_idx0[NCENT * 16];
__device__ int   g_idx1[NCENT * 32];
__device__ int   g_idx2[NCENT * 128];

// =====================================================================
// FPS: one block per batch, 1024 threads, register-resident distances,
// one barrier/iter, rotating 3-slot 64-bit atomicMax key (JAX tie-break).
// =====================================================================
__global__ __launch_bounds__(1024) void fps_kernel(const float* __restrict__ xyz,
                                                   float* __restrict__ out_newxyz)
{
    int b = blockIdx.x;
    extern __shared__ float sm[];
    float* sx = sm;
    float* sy = sm + NPTS;
    float* sz = sm + 2 * NPTS;
    __shared__ unsigned long long skey[3];

    const float* base = xyz + (size_t)b * NPTS * 3;
    float px[4], py[4], pz[4], pd[4];
    #pragma unroll
    for (int r = 0; r < 4; r++) {
        int p = threadIdx.x + r * 1024;
        float x = base[p * 3 + 0];
        float y = base[p * 3 + 1];
        float z = base[p * 3 + 2];
        sx[p] = x; sy[p] = y; sz[p] = z;
        px[r] = x; py[r] = y; pz[r] = z;
        pd[r] = 1e10f;
    }
    if (threadIdx.x == 0) {
        skey[0] = 0xFFFFFFFFull;
        skey[1] = 0ull;
        skey[2] = 0ull;
    }
    __syncthreads();

    int lane = threadIdx.x & 31;

    for (int it = 0; it < NPOINT; it++) {
        int cur = it % 3, nxt = (it + 1) % 3, rst = (it + 2) % 3;
        unsigned int low = (unsigned int)skey[cur];
        int far = (int)(0xFFFFFFFFu - low);

        if (threadIdx.x == 0) {
            float fx = sx[far], fy = sy[far], fz = sz[far];
            int row = b * NPOINT + it;
            out_newxyz[row * 3 + 0] = fx;
            out_newxyz[row * 3 + 1] = fy;
            out_newxyz[row * 3 + 2] = fz;
            g_new_xyz[row * 3 + 0] = fx;
            g_new_xyz[row * 3 + 1] = fy;
            g_new_xyz[row * 3 + 2] = fz;
            skey[rst] = 0ull;
        }
        float cx = sx[far], cy = sy[far], cz = sz[far];

        float bv = -1.0f;
        int   bi = 0;
        #pragma unroll
        for (int r = 0; r < 4; r++) {
            float dx = px[r] - cx;
            float dy = py[r] - cy;
            float dz = pz[r] - cz;
            float d = __fadd_rn(__fadd_rn(__fmul_rn(dx, dx), __fmul_rn(dy, dy)),
                                __fmul_rn(dz, dz));
            float nd = fminf(pd[r], d);
            pd[r] = nd;
            if (nd > bv) { bv = nd; bi = threadIdx.x + r * 1024; }
        }
        #pragma unroll
        for (int off = 16; off >= 1; off >>= 1) {
            float ov = __shfl_down_sync(0xffffffffu, bv, off);
            int   oi = __shfl_down_sync(0xffffffffu, bi, off);
            if (ov > bv || (ov == bv && oi < bi)) { bv = ov; bi = oi; }
        }
        if (lane == 0) {
            unsigned long long key =
                ((unsigned long long)__float_as_uint(bv) << 32) |
                (unsigned long long)(0xFFFFFFFFu - (unsigned int)bi);
            atomicMax(&skey[nxt], key);
        }
        __syncthreads();
    }
}

// =====================================================================
// Fused ball query (3 radii, one smem-staged scan). Warp per center.
// =====================================================================
__global__ __launch_bounds__(256) void bq_fused_kernel(const float* __restrict__ xyz,
                                                       int* __restrict__ o0,
                                                       int* __restrict__ o1,
                                                       int* __restrict__ o2)
{
    extern __shared__ float sm[];
    float* sx = sm;
    float* sy = sm + NPTS;
    float* sz = sm + 2 * NPTS;

    int wid  = threadIdx.x >> 5;
    int lane = threadIdx.x & 31;
    int gw   = blockIdx.x * 8 + wid;
    int b    = gw >> 10;

    const float* base = xyz + (size_t)b * NPTS * 3;
    for (int t = threadIdx.x; t < NPTS * 3; t += 256) {
        int p = t / 3, c = t - p * 3;
        float v = base[t];
        (c == 0 ? sx : (c == 1 ? sy : sz))[p] = v;
    }
    __syncthreads();

    const float r2_0 = (float)(0.1 * 0.1);
    const float r2_1 = (float)(0.2 * 0.2);
    const float r2_2 = (float)(0.4 * 0.4);

    float cx = g_new_xyz[gw * 3 + 0];
    float cy = g_new_xyz[gw * 3 + 1];
    float cz = g_new_xyz[gw * 3 + 2];

    int* p0 = o0 + (size_t)gw * 16;
    int* p1 = o1 + (size_t)gw * 32;
    int* p2 = o2 + (size_t)gw * 128;

    int c0 = 0, c1 = 0, c2 = 0;
    int f0 = -1, f1 = -1, f2 = -1;
    unsigned lmask = (1u << lane) - 1u;

    for (int s = 0; s < NPTS; s += 32) {
        int p = s + lane;
        float dx = sx[p] - cx;
        float dy = sy[p] - cy;
        float dz = sz[p] - cz;
        float d2 = __fadd_rn(__fadd_rn(__fmul_rn(dx, dx), __fmul_rn(dy, dy)),
                             __fmul_rn(dz, dz));
        bool h0 = d2 < r2_0, h1 = d2 < r2_1, h2 = d2 < r2_2;
        unsigned m0 = __ballot_sync(0xffffffffu, h0);
        unsigned m1 = __ballot_sync(0xffffffffu, h1);
        unsigned m2 = __ballot_sync(0xffffffffu, h2);
        if (m0) {
            if (f0 < 0) f0 = s + (__ffs(m0) - 1);
            if (h0) { int pos = c0 + __popc(m0 & lmask); if (pos < 16) p0[pos] = p; }
            c0 += __popc(m0);
        }
        if (m1) {
            if (f1 < 0) f1 = s + (__ffs(m1) - 1);
            if (h1) { int pos = c1 + __popc(m1 & lmask); if (pos < 32) p1[pos] = p; }
            c1 += __popc(m1);
        }
        if (m2) {
            if (f2 < 0) f2 = s + (__ffs(m2) - 1);
            if (h2) { int pos = c2 + __popc(m2 & lmask); if (pos < 128) p2[pos] = p; }
            c2 += __popc(m2);
        }
        if (c0 >= 16 && c1 >= 32 && c2 >= 128) break;
    }
    for (int pos = c0 + lane; pos < 16; pos += 32) p0[pos] = f0;
    for (int pos = c1 + lane; pos < 32; pos += 32) p1[pos] = f1;
    for (int pos = c2 + lane; pos < 128; pos += 32) p2[pos] = f2;
}

// =====================================================================
// Unified tf32 mma MLP. One block = 128 rows = (128/SEG) centers.
// 8 warps: 4 m-warps (32 rows) x 2 n-warps.
// =====================================================================
__device__ __forceinline__ uint32_t f2tf32(float f) {
    uint32_t r; asm("cvt.rna.tf32.f32 %0, %1;" : "=r"(r) : "f"(f)); return r;
}

__device__ __forceinline__ void mma_tf32(float* d, const uint32_t* a, const uint32_t* b) {
    asm volatile("mma.sync.aligned.m16n8k8.row.col.f32.tf32.tf32.f32 "
                 "{%0,%1,%2,%3},{%4,%5,%6,%7},{%8,%9},{%0,%1,%2,%3};"
                 : "+f"(d[0]), "+f"(d[1]), "+f"(d[2]), "+f"(d[3])
                 : "r"(a[0]), "r"(a[1]), "r"(a[2]), "r"(a[3]),
                   "r"(b[0]), "r"(b[1]));
}

#define S_IN 76   // input stride: 67 used, pad to 72 zeros, ≡12 mod 32 (conflict-free)

// MODE: 0 = relu+bias -> sOut ; 1 = final maxpool
template<int KSTEPS, int SA, int NP, int NT, int SOUT, int SEG, int MODE>
__device__ __forceinline__ void mma_layer(const float* __restrict__ sA,
                                          const float* __restrict__ sW,
                                          const float* __restrict__ gBias,
                                          float* __restrict__ sOut,
                                          int* __restrict__ sMaxI,
                                          float* __restrict__ outF, int centerBase)
{
    int lane = threadIdx.x & 31;
    int w    = threadIdx.x >> 5;
    int g    = lane >> 2;
    int tg   = lane & 3;
    int m0   = (w >> 1) * 32;
    int n0   = (w & 1) * (NT * 8);

    float acc[2][NT][4];
    #pragma unroll
    for (int mt = 0; mt < 2; mt++)
        #pragma unroll
        for (int nt = 0; nt < NT; nt++)
            #pragma unroll
            for (int i = 0; i < 4; i++) acc[mt][nt][i] = 0.0f;

    for (int ks = 0; ks < KSTEPS; ks++) {
        int k0 = ks * 8;
        uint32_t a[2][4];
        #pragma unroll
        for (int mt = 0; mt < 2; mt++) {
            const float* Ab = sA + (m0 + 16 * mt) * SA + k0;
            a[mt][0] = f2tf32(Ab[g * SA + tg]);
            a[mt][1] = f2tf32(Ab[(g + 8) * SA + tg]);
            a[mt][2] = f2tf32(Ab[g * SA + tg + 4]);
            a[mt][3] = f2tf32(Ab[(g + 8) * SA + tg + 4]);
        }
        #pragma unroll
        for (int nt = 0; nt < NT; nt++) {
            const float* Wb = sW + k0 * NP + n0 + 8 * nt;
            uint32_t bfr[2];
            bfr[0] = f2tf32(Wb[tg * NP + g]);
            bfr[1] = f2tf32(Wb[(tg + 4) * NP + g]);
            mma_tf32(acc[0][nt], a[0], bfr);
            mma_tf32(acc[1][nt], a[1], bfr);
        }
    }

    if (MODE == 0) {
        #pragma unroll
        for (int mt = 0; mt < 2; mt++)
            #pragma unroll
            for (int nt = 0; nt < NT; nt++) {
                int row = m0 + 16 * mt + g;
                int col = n0 + 8 * nt + 2 * tg;
                float b0v = gBias[col], b1v = gBias[col + 1];
                sOut[row * SOUT + col]           = fmaxf(acc[mt][nt][0] + b0v, 0.0f);
                sOut[row * SOUT + col + 1]       = fmaxf(acc[mt][nt][1] + b1v, 0.0f);
                sOut[(row + 8) * SOUT + col]     = fmaxf(acc[mt][nt][2] + b0v, 0.0f);
                sOut[(row + 8) * SOUT + col + 1] = fmaxf(acc[mt][nt][3] + b1v, 0.0f);
            }
    } else if (SEG == 128) {
        // all 4 m-warps cover one center: shared atomicMax
        #pragma unroll
        for (int nt = 0; nt < NT; nt++) {
            int col = n0 + 8 * nt + 2 * tg;
            float b0v = gBias[col], b1v = gBias[col + 1];
            float v0 = fmaxf(fmaxf(acc[0][nt][0], acc[0][nt][2]),
                             fmaxf(acc[1][nt][0], acc[1][nt][2]));
            float v1 = fmaxf(fmaxf(acc[0][nt][1], acc[0][nt][3]),
                             fmaxf(acc[1][nt][1], acc[1][nt][3]));
            v0 = fmaxf(v0 + b0v, 0.0f);
            v1 = fmaxf(v1 + b1v, 0.0f);
            #pragma unroll
            for (int off = 4; off < 32; off <<= 1) {
                v0 = fmaxf(v0, __shfl_xor_sync(0xffffffffu, v0, off));
                v1 = fmaxf(v1, __shfl_xor_sync(0xffffffffu, v1, off));
            }
            if (g == 0) {
                atomicMax(&sMaxI[col],     __float_as_int(v0));
                atomicMax(&sMaxI[col + 1], __float_as_int(v1));
            }
        }
    } else if (SEG == 32) {
        // one warp (32 rows) == one center
        int center = centerBase + (w >> 1);
        #pragma unroll
        for (int nt = 0; nt < NT; nt++) {
            int col = n0 + 8 * nt + 2 * tg;
            float v0 = fmaxf(fmaxf(acc[0][nt][0], acc[0][nt][2]),
                             fmaxf(acc[1][nt][0], acc[1][nt][2]));
            float v1 = fmaxf(fmaxf(acc[0][nt][1], acc[0][nt][3]),
                             fmaxf(acc[1][nt][1], acc[1][nt][3]));
            #pragma unroll
            for (int off = 4; off < 32; off <<= 1) {
                v0 = fmaxf(v0, __shfl_xor_sync(0xffffffffu, v0, off));
                v1 = fmaxf(v1, __shfl_xor_sync(0xffffffffu, v1, off));
            }
            if (g == 0) {
                float* op = outF + (size_t)center * FEAT_W;
                op[col]     = fmaxf(v0 + gBias[col], 0.0f);
                op[col + 1] = fmaxf(v1 + gBias[col + 1], 0.0f);
            }
        }
    } else { // SEG == 16: each m-tile (mt) is one center
        #pragma unroll
        for (int mt = 0; mt < 2; mt++) {
            int center = centerBase + (w >> 1) * 2 + mt;
            #pragma unroll
            for (int nt = 0; nt < NT; nt++) {
                int col = n0 + 8 * nt + 2 * tg;
                float v0 = fmaxf(acc[mt][nt][0], acc[mt][nt][2]);
                float v1 = fmaxf(acc[mt][nt][1], acc[mt][nt][3]);
                #pragma unroll
                for (int off = 4; off < 32; off <<= 1) {
                    v0 = fmaxf(v0, __shfl_xor_sync(0xffffffffu, v0, off));
                    v1 = fmaxf(v1, __shfl_xor_sync(0xffffffffu, v1, off));
                }
                if (g == 0) {
                    float* op = outF + (size_t)center * FEAT_W;
                    op[col]     = fmaxf(v0 + gBias[col], 0.0f);
                    op[col + 1] = fmaxf(v1 + gBias[col + 1], 0.0f);
                }
            }
        }
    }
}

template<int ROWS, int KR, int NC, int NP>
__device__ __forceinline__ void stage_w(float* __restrict__ sW, const float* __restrict__ gW)
{
    for (int t = threadIdx.x; t < ROWS * NP; t += 256) {
        int r = t / NP, c = t - r * NP;
        sW[t] = (r < KR && c < NC) ? gW[r * NC + c] : 0.0f;
    }
}

__host__ __device__ constexpr int cmax3i(int a, int b, int c) {
    return a > b ? (a > c ? a : c) : (b > c ? b : c);
}

// SEG samples/center, CPB = 128/SEG centers/block.
template<int SEG, int C1, int C2, int C3>
__global__ __launch_bounds__(256) void mlp_mma_kernel(const float* __restrict__ xyz,
                                                      const float* __restrict__ points,
                                                      const int* __restrict__ idxbuf,
                                                      const float* __restrict__ W1, const float* __restrict__ B1,
                                                      const float* __restrict__ W2, const float* __restrict__ B2,
                                                      const float* __restrict__ W3, const float* __restrict__ B3,
                                                      float* __restrict__ outF)
{
    constexpr int CPB = 128 / SEG;
    constexpr int S1 = C1 + 4, S2 = C2 + 4;
    constexpr int NP1 = C1 + 8, NP2 = C2 + 8, NP3 = C3 + 8;
    constexpr int WMAX = cmax3i(72 * NP1, C1 * NP2, C2 * NP3);
    constexpr int KS2 = C1 / 8, KS3 = C2 / 8;

    extern __shared__ float sm[];
    float* sIn  = sm;                  // 128 * S_IN
    float* buf1 = sIn + 128 * S_IN;    // 128 * S1
    float* buf2 = buf1 + 128 * S1;     // 128 * S2
    float* sW   = buf2 + 128 * S2;     // WMAX
    int*   sMaxI = (int*)(sW + WMAX);  // 128
    int*   sIdx  = sMaxI + 128;        // 128

    int centerBase = blockIdx.x * CPB;
    int b = centerBase >> 10;

    for (int t = threadIdx.x; t < 128; t += 256) {
        sIdx[t]  = idxbuf[(size_t)centerBase * SEG + t];
        sMaxI[t] = 0;
    }
    __syncthreads();

    const float* pB = points + (size_t)b * NPTS * CIN_PTS;
    const float* xB = xyz + (size_t)b * NPTS * 3;

    for (int t = threadIdx.x; t < 128 * S_IN; t += 256) {
        int s = t / S_IN, c = t - s * S_IN;
        int ci = centerBase + s / SEG;
        float v;
        if (c < 64)       v = pB[(size_t)sIdx[s] * CIN_PTS + c];
        else if (c < 67) {
            int d = c - 64;
            v = xB[(size_t)sIdx[s] * 3 + d] - g_new_xyz[ci * 3 + d];
        } else v = 0.0f;
        sIn[t] = v;
    }
    stage_w<72, 67, C1, NP1>(sW, W1);
    __syncthreads();

    mma_layer<9, S_IN, NP1, C1/16, S1, SEG, 0>(sIn, sW, B1, buf1, sMaxI, outF, centerBase);
    __syncthreads();

    stage_w<C1, C1, C2, NP2>(sW, W2);
    __syncthreads();

    mma_layer<KS2, S1, NP2, C2/16, S2, SEG, 0>(buf1, sW, B2, buf2, sMaxI, outF, centerBase);
    __syncthreads();

    stage_w<C2, C2, C3, NP3>(sW, W3);
    __syncthreads();

    mma_layer<KS3, S2, NP3, C3/16, 0, SEG, 1>(buf2, sW, B3, nullptr, sMaxI, outF, centerBase);

    if (SEG == 128) {
        __syncthreads();
        for (int t = threadIdx.x; t < C3; t += 256)
            outF[(size_t)centerBase * FEAT_W + t] = __int_as_float(sMaxI[t]);
    }
}

// =====================================================================
// host launch
// =====================================================================
template<int SEG, int C1, int C2, int C3>
static int smem_mma() {
    int S1 = C1 + 4, S2 = C2 + 4;
    int WMAX = cmax3i(72 * (C1 + 8), C1 * (C2 + 8), C2 * (C3 + 8));
    return (128 * S_IN + 128 * S1 + 128 * S2 + WMAX + 256) * 4;
}

extern "C" void kernel_launch(void* const* d_in, const int* in_sizes, int n_in,
                              void* d_out, int out_size)
{
    const float* xyz = (const float*)d_in[0];
    const float* pts = (const float*)d_in[1];
    const float* W[3][3];
    const float* Bv[3][3];
    int k = 2;
    for (int bi = 0; bi < 3; bi++)
        for (int li = 0; li < 3; li++) {
            W[bi][li]  = (const float*)d_in[k++];
            Bv[bi][li] = (const float*)d_in[k++];
        }

    float* out        = (float*)d_out;
    float* out_newxyz = out;
    float* out_feat   = out + (size_t)NCENT * 3;

    const int fps_smem = 3 * NPTS * 4;
    const int bq_smem  = 3 * NPTS * 4;
    const int sm0 = smem_mma<16, 32, 32, 64>();
    const int sm1 = smem_mma<32, 64, 64, 128>();
    const int sm2 = smem_mma<128, 64, 96, 128>();

    cudaFuncSetAttribute(fps_kernel, cudaFuncAttributeMaxDynamicSharedMemorySize, fps_smem);
    cudaFuncSetAttribute((const void*)mlp_mma_kernel<16, 32, 32, 64>,
                         cudaFuncAttributeMaxDynamicSharedMemorySize, sm0);
    cudaFuncSetAttribute((const void*)mlp_mma_kernel<32, 64, 64, 128>,
                         cudaFuncAttributeMaxDynamicSharedMemorySize, sm1);
    cudaFuncSetAttribute((const void*)mlp_mma_kernel<128, 64, 96, 128>,
                         cudaFuncAttributeMaxDynamicSharedMemorySize, sm2);

    fps_kernel<<<BATCH, 1024, fps_smem>>>(xyz, out_newxyz);
    bq_fused_kernel<<<NCENT / 8, 256, bq_smem>>>(xyz, g_idx0, g_idx1, g_idx2);

    mlp_mma_kernel<16, 32, 32, 64><<<NCENT / 8, 256, sm0>>>(
        xyz, pts, g_idx0,
        W[0][0], Bv[0][0], W[0][1], Bv[0][1], W[0][2], Bv[0][2],
        out_feat + 0);
    mlp_mma_kernel<32, 64, 64, 128><<<NCENT / 4, 256, sm1>>>(
        xyz, pts, g_idx1,
        W[1][0], Bv[1][0], W[1][1], Bv[1][1], W[1][2], Bv[1][2],
        out_feat + 64);
    mlp_mma_kernel<128, 64, 96, 128><<<NCENT, 256, sm2>>>(
        xyz, pts, g_idx2,
        W[2][0], Bv[2][0], W[2][1], Bv[2][1], W[2][2], Bv[2][2],
        out_feat + 192);
}

// round 5
// speedup vs baseline: 1.8661x; 1.3000x over previous
#include <cuda_runtime.h>
#include <cuda_bf16.h>
#include <cstdint>

#define BATCH   8
#define NPTS    4096
#define CIN_PTS 64
#define NPOINT  1024
#define NCENT   (BATCH * NPOINT)   // 8192
#define FEAT_W  320
#define S_IN    76                 // input stride: 67 used + zero pad
#define NTH     512                // threads per MLP block

// ---------------- device scratch ----------------
__device__ float g_new_xyz[NCENT * 3];
__device__ int   g_idx0[NCENT * 16];
__device__ int   g_idx1[NCENT * 32];
__device__ int   g_idx2[NCENT * 128];

__host__ __device__ constexpr int cmax3i(int a, int b, int c) {
    return a > b ? (a > c ? a : c) : (b > c ? b : c);
}

// =====================================================================
// FPS: one block per batch, 256 threads x 16 register-resident points.
// One warp-reduce + one shared 64-bit atomicMax per warp per iteration.
// Key = (float bits of dist << 32) | (~index)  ==> JAX first-index tie-break.
// =====================================================================
__global__ __launch_bounds__(256) void fps_kernel(const float* __restrict__ xyz,
                                                  float* __restrict__ out_newxyz)
{
    int b = blockIdx.x;
    extern __shared__ float sm[];
    float* sx = sm;
    float* sy = sm + NPTS;
    float* sz = sm + 2 * NPTS;
    __shared__ unsigned long long skey[3];

    const float* base = xyz + (size_t)b * NPTS * 3;
    float px[16], py[16], pz[16], pd[16];
    #pragma unroll
    for (int r = 0; r < 16; r++) {
        int p = threadIdx.x + r * 256;
        float x = base[p * 3 + 0];
        float y = base[p * 3 + 1];
        float z = base[p * 3 + 2];
        sx[p] = x; sy[p] = y; sz[p] = z;
        px[r] = x; py[r] = y; pz[r] = z;
        pd[r] = 1e10f;
    }
    if (threadIdx.x == 0) {
        skey[0] = 0xFFFFFFFFull;   // decodes to index 0
        skey[1] = 0ull;
        skey[2] = 0ull;
    }
    __syncthreads();

    int lane = threadIdx.x & 31;

    for (int it = 0; it < NPOINT; it++) {
        int cur = it % 3, nxt = (it + 1) % 3, rst = (it + 2) % 3;
        unsigned int low = (unsigned int)skey[cur];
        int far = (int)(0xFFFFFFFFu - low);

        if (threadIdx.x == 0) {
            float fx = sx[far], fy = sy[far], fz = sz[far];
            int row = b * NPOINT + it;
            out_newxyz[row * 3 + 0] = fx;
            out_newxyz[row * 3 + 1] = fy;
            out_newxyz[row * 3 + 2] = fz;
            g_new_xyz[row * 3 + 0] = fx;
            g_new_xyz[row * 3 + 1] = fy;
            g_new_xyz[row * 3 + 2] = fz;
            skey[rst] = 0ull;
        }
        float cx = sx[far], cy = sy[far], cz = sz[far];

        float bv = -1.0f;
        int   bi = 0;
        #pragma unroll
        for (int r = 0; r < 16; r++) {
            float dx = px[r] - cx;
            float dy = py[r] - cy;
            float dz = pz[r] - cz;
            float d = __fadd_rn(__fadd_rn(__fmul_rn(dx, dx), __fmul_rn(dy, dy)),
                                __fmul_rn(dz, dz));
            float nd = fminf(pd[r], d);
            pd[r] = nd;
            if (nd > bv) { bv = nd; bi = threadIdx.x + r * 256; }
        }
        #pragma unroll
        for (int off = 16; off >= 1; off >>= 1) {
            float ov = __shfl_down_sync(0xffffffffu, bv, off);
            int   oi = __shfl_down_sync(0xffffffffu, bi, off);
            if (ov > bv || (ov == bv && oi < bi)) { bv = ov; bi = oi; }
        }
        if (lane == 0) {
            unsigned long long key =
                ((unsigned long long)__float_as_uint(bv) << 32) |
                (unsigned long long)(0xFFFFFFFFu - (unsigned int)bi);
            atomicMax(&skey[nxt], key);
        }
        __syncthreads();
    }
}

// =====================================================================
// Fused ball query (3 radii, one smem-staged scan). Warp per center.
// =====================================================================
__global__ __launch_bounds__(256) void bq_fused_kernel(const float* __restrict__ xyz,
                                                       int* __restrict__ o0,
                                                       int* __restrict__ o1,
                                                       int* __restrict__ o2)
{
    extern __shared__ float sm[];
    float* sx = sm;
    float* sy = sm + NPTS;
    float* sz = sm + 2 * NPTS;

    int wid  = threadIdx.x >> 5;
    int lane = threadIdx.x & 31;
    int gw   = blockIdx.x * 8 + wid;
    int b    = gw >> 10;

    const float* base = xyz + (size_t)b * NPTS * 3;
    for (int t = threadIdx.x; t < NPTS * 3; t += 256) {
        int p = t / 3, c = t - p * 3;
        float v = base[t];
        (c == 0 ? sx : (c == 1 ? sy : sz))[p] = v;
    }
    __syncthreads();

    const float r2_0 = (float)(0.1 * 0.1);
    const float r2_1 = (float)(0.2 * 0.2);
    const float r2_2 = (float)(0.4 * 0.4);

    float cx = g_new_xyz[gw * 3 + 0];
    float cy = g_new_xyz[gw * 3 + 1];
    float cz = g_new_xyz[gw * 3 + 2];

    int* p0 = o0 + (size_t)gw * 16;
    int* p1 = o1 + (size_t)gw * 32;
    int* p2 = o2 + (size_t)gw * 128;

    int c0 = 0, c1 = 0, c2 = 0;
    int f0 = -1, f1 = -1, f2 = -1;
    unsigned lmask = (1u << lane) - 1u;

    for (int s = 0; s < NPTS; s += 32) {
        int p = s + lane;
        float dx = sx[p] - cx;
        float dy = sy[p] - cy;
        float dz = sz[p] - cz;
        float d2 = __fadd_rn(__fadd_rn(__fmul_rn(dx, dx), __fmul_rn(dy, dy)),
                             __fmul_rn(dz, dz));
        bool h0 = d2 < r2_0, h1 = d2 < r2_1, h2 = d2 < r2_2;
        unsigned m0 = __ballot_sync(0xffffffffu, h0);
        unsigned m1 = __ballot_sync(0xffffffffu, h1);
        unsigned m2 = __ballot_sync(0xffffffffu, h2);
        if (m0) {
            if (f0 < 0) f0 = s + (__ffs(m0) - 1);
            if (h0) { int pos = c0 + __popc(m0 & lmask); if (pos < 16) p0[pos] = p; }
            c0 += __popc(m0);
        }
        if (m1) {
            if (f1 < 0) f1 = s + (__ffs(m1) - 1);
            if (h1) { int pos = c1 + __popc(m1 & lmask); if (pos < 32) p1[pos] = p; }
            c1 += __popc(m1);
        }
        if (m2) {
            if (f2 < 0) f2 = s + (__ffs(m2) - 1);
            if (h2) { int pos = c2 + __popc(m2 & lmask); if (pos < 128) p2[pos] = p; }
            c2 += __popc(m2);
        }
        if (c0 >= 16 && c1 >= 32 && c2 >= 128) break;
    }
    for (int pos = c0 + lane; pos < 16; pos += 32) p0[pos] = f0;
    for (int pos = c1 + lane; pos < 32; pos += 32) p1[pos] = f1;
    for (int pos = c2 + lane; pos < 128; pos += 32) p2[pos] = f2;
}

// =====================================================================
// tf32 mma building blocks. 512 threads: 4 m-warps (w>>2) x 4 n-warps (w&3).
// =====================================================================
__device__ __forceinline__ uint32_t f2tf32(float f) {
    uint32_t r; asm("cvt.rna.tf32.f32 %0, %1;" : "=r"(r) : "f"(f)); return r;
}

__device__ __forceinline__ void mma_tf32(float* d, const uint32_t* a, const uint32_t* b) {
    asm volatile("mma.sync.aligned.m16n8k8.row.col.f32.tf32.tf32.f32 "
                 "{%0,%1,%2,%3},{%4,%5,%6,%7},{%8,%9},{%0,%1,%2,%3};"
                 : "+f"(d[0]), "+f"(d[1]), "+f"(d[2]), "+f"(d[3])
                 : "r"(a[0]), "r"(a[1]), "r"(a[2]), "r"(a[3]),
                   "r"(b[0]), "r"(b[1]));
}

template<int KSTEPS, int SA, int NP, int NT>
__device__ __forceinline__ void mma_accum(const float* __restrict__ sA,
                                          const float* __restrict__ sW,
                                          float (&acc)[2][NT][4])
{
    int lane = threadIdx.x & 31;
    int w    = threadIdx.x >> 5;
    int g    = lane >> 2;
    int tg   = lane & 3;
    int m0   = (w >> 2) * 32;
    int n0   = (w & 3) * (NT * 8);

    for (int ks = 0; ks < KSTEPS; ks++) {
        int k0 = ks * 8;
        uint32_t a[2][4];
        #pragma unroll
        for (int mt = 0; mt < 2; mt++) {
            const float* Ab = sA + (m0 + 16 * mt) * SA + k0;
            a[mt][0] = f2tf32(Ab[g * SA + tg]);
            a[mt][1] = f2tf32(Ab[(g + 8) * SA + tg]);
            a[mt][2] = f2tf32(Ab[g * SA + tg + 4]);
            a[mt][3] = f2tf32(Ab[(g + 8) * SA + tg + 4]);
        }
        #pragma unroll
        for (int nt = 0; nt < NT; nt++) {
            const float* Wb = sW + k0 * NP + n0 + 8 * nt;
            uint32_t bfr[2];
            bfr[0] = f2tf32(Wb[tg * NP + g]);
            bfr[1] = f2tf32(Wb[(tg + 4) * NP + g]);
            mma_tf32(acc[0][nt], a[0], bfr);
            mma_tf32(acc[1][nt], a[1], bfr);
        }
    }
}

template<int NT, int SOUT>
__device__ __forceinline__ void epi_relu(float (&acc)[2][NT][4],
                                         const float* __restrict__ gBias,
                                         float* __restrict__ sOut)
{
    int lane = threadIdx.x & 31;
    int w    = threadIdx.x >> 5;
    int g    = lane >> 2;
    int tg   = lane & 3;
    int m0   = (w >> 2) * 32;
    int n0   = (w & 3) * (NT * 8);
    #pragma unroll
    for (int mt = 0; mt < 2; mt++)
        #pragma unroll
        for (int nt = 0; nt < NT; nt++) {
            int row = m0 + 16 * mt + g;
            int col = n0 + 8 * nt + 2 * tg;
            float b0v = gBias[col], b1v = gBias[col + 1];
            sOut[row * SOUT + col]           = fmaxf(acc[mt][nt][0] + b0v, 0.0f);
            sOut[row * SOUT + col + 1]       = fmaxf(acc[mt][nt][1] + b1v, 0.0f);
            sOut[(row + 8) * SOUT + col]     = fmaxf(acc[mt][nt][2] + b0v, 0.0f);
            sOut[(row + 8) * SOUT + col + 1] = fmaxf(acc[mt][nt][3] + b1v, 0.0f);
        }
}

template<int NT, int SEG>
__device__ __forceinline__ void epi_final(float (&acc)[2][NT][4],
                                          const float* __restrict__ gBias,
                                          int* __restrict__ sMaxI,
                                          float* __restrict__ outF, int centerBase)
{
    int lane = threadIdx.x & 31;
    int w    = threadIdx.x >> 5;
    int g    = lane >> 2;
    int tg   = lane & 3;
    int n0   = (w & 3) * (NT * 8);

    if (SEG == 128) {
        #pragma unroll
        for (int nt = 0; nt < NT; nt++) {
            int col = n0 + 8 * nt + 2 * tg;
            float v0 = fmaxf(fmaxf(acc[0][nt][0], acc[0][nt][2]),
                             fmaxf(acc[1][nt][0], acc[1][nt][2]));
            float v1 = fmaxf(fmaxf(acc[0][nt][1], acc[0][nt][3]),
                             fmaxf(acc[1][nt][1], acc[1][nt][3]));
            v0 = fmaxf(v0 + gBias[col], 0.0f);
            v1 = fmaxf(v1 + gBias[col + 1], 0.0f);
            #pragma unroll
            for (int off = 4; off < 32; off <<= 1) {
                v0 = fmaxf(v0, __shfl_xor_sync(0xffffffffu, v0, off));
                v1 = fmaxf(v1, __shfl_xor_sync(0xffffffffu, v1, off));
            }
            if (g == 0) {
                atomicMax(&sMaxI[col],     __float_as_int(v0));
                atomicMax(&sMaxI[col + 1], __float_as_int(v1));
            }
        }
    } else if (SEG == 32) {
        int center = centerBase + (w >> 2);
        #pragma unroll
        for (int nt = 0; nt < NT; nt++) {
            int col = n0 + 8 * nt + 2 * tg;
            float v0 = fmaxf(fmaxf(acc[0][nt][0], acc[0][nt][2]),
                             fmaxf(acc[1][nt][0], acc[1][nt][2]));
            float v1 = fmaxf(fmaxf(acc[0][nt][1], acc[0][nt][3]),
                             fmaxf(acc[1][nt][1], acc[1][nt][3]));
            #pragma unroll
            for (int off = 4; off < 32; off <<= 1) {
                v0 = fmaxf(v0, __shfl_xor_sync(0xffffffffu, v0, off));
                v1 = fmaxf(v1, __shfl_xor_sync(0xffffffffu, v1, off));
            }
            if (g == 0) {
                float* op = outF + (size_t)center * FEAT_W;
                op[col]     = fmaxf(v0 + gBias[col], 0.0f);
                op[col + 1] = fmaxf(v1 + gBias[col + 1], 0.0f);
            }
        }
    } else { // SEG == 16: each m-tile (mt) is one center
        #pragma unroll
        for (int mt = 0; mt < 2; mt++) {
            int center = centerBase + (w >> 2) * 2 + mt;
            #pragma unroll
            for (int nt = 0; nt < NT; nt++) {
                int col = n0 + 8 * nt + 2 * tg;
                float v0 = fmaxf(acc[mt][nt][0], acc[mt][nt][2]);
                float v1 = fmaxf(acc[mt][nt][1], acc[mt][nt][3]);
                #pragma unroll
                for (int off = 4; off < 32; off <<= 1) {
                    v0 = fmaxf(v0, __shfl_xor_sync(0xffffffffu, v0, off));
                    v1 = fmaxf(v1, __shfl_xor_sync(0xffffffffu, v1, off));
                }
                if (g == 0) {
                    float* op = outF + (size_t)center * FEAT_W;
                    op[col]     = fmaxf(v0 + gBias[col], 0.0f);
                    op[col + 1] = fmaxf(v1 + gBias[col + 1], 0.0f);
                }
            }
        }
    }
}

template<int ROWS, int KR, int NC, int NP>
__device__ __forceinline__ void stage_w(float* __restrict__ sW, const float* __restrict__ gW)
{
    for (int t = threadIdx.x; t < ROWS * NP; t += NTH) {
        int r = t / NP, c = t - r * NP;
        sW[t] = (r < KR && c < NC) ? gW[r * NC + c] : 0.0f;
    }
}

// =====================================================================
// Unified MLP kernel (round-3 layout, 512 threads). One block = 128 rows.
// =====================================================================
template<int SEG, int C1, int C2, int C3>
__global__ __launch_bounds__(NTH) void mlp_mma_kernel(const float* __restrict__ xyz,
                                                      const float* __restrict__ points,
                                                      const int* __restrict__ idxbuf,
                                                      const float* __restrict__ W1, const float* __restrict__ B1,
                                                      const float* __restrict__ W2, const float* __restrict__ B2,
                                                      const float* __restrict__ W3, const float* __restrict__ B3,
                                                      float* __restrict__ outF)
{
    constexpr int CPB = 128 / SEG;
    constexpr int S1 = C1 + 4, S2 = C2 + 4;
    constexpr int NP1 = C1 + 8, NP2 = C2 + 8, NP3 = C3 + 8;
    constexpr int WMAX = cmax3i(72 * NP1, C1 * NP2, C2 * NP3);
    constexpr int KS2 = C1 / 8, KS3 = C2 / 8;
    constexpr int NT1 = C1 / 32, NT2 = C2 / 32, NT3 = C3 / 32;

    extern __shared__ float sm[];
    float* sIn  = sm;                  // 128 * S_IN
    float* buf1 = sIn + 128 * S_IN;    // 128 * S1
    float* buf2 = buf1 + 128 * S1;     // 128 * S2
    float* sW   = buf2 + 128 * S2;     // WMAX
    int*   sMaxI = (int*)(sW + WMAX);  // 128
    int*   sIdx  = sMaxI + 128;        // 128

    int centerBase = blockIdx.x * CPB;
    int b = centerBase >> 10;

    for (int t = threadIdx.x; t < 128; t += NTH) {
        sIdx[t]  = idxbuf[(size_t)centerBase * SEG + t];
        sMaxI[t] = 0;
    }
    __syncthreads();

    const float* pB = points + (size_t)b * NPTS * CIN_PTS;
    const float* xB = xyz + (size_t)b * NPTS * 3;

    for (int t = threadIdx.x; t < 128 * S_IN; t += NTH) {
        int s = t / S_IN, c = t - s * S_IN;
        int ci = centerBase + s / SEG;
        float v;
        if (c < 64)       v = pB[(size_t)sIdx[s] * CIN_PTS + c];
        else if (c < 67) {
            int d = c - 64;
            v = xB[(size_t)sIdx[s] * 3 + d] - g_new_xyz[ci * 3 + d];
        } else v = 0.0f;
        sIn[t] = v;
    }
    stage_w<72, 67, C1, NP1>(sW, W1);
    __syncthreads();

    // layer 1
    {
        float acc[2][NT1][4];
        #pragma unroll
        for (int mt = 0; mt < 2; mt++)
            #pragma unroll
            for (int nt = 0; nt < NT1; nt++)
                #pragma unroll
                for (int i = 0; i < 4; i++) acc[mt][nt][i] = 0.0f;
        mma_accum<9, S_IN, NP1, NT1>(sIn, sW, acc);
        epi_relu<NT1, S1>(acc, B1, buf1);
    }
    __syncthreads();

    stage_w<C1, C1, C2, NP2>(sW, W2);
    __syncthreads();

    // layer 2
    {
        float acc[2][NT2][4];
        #pragma unroll
        for (int mt = 0; mt < 2; mt++)
            #pragma unroll
            for (int nt = 0; nt < NT2; nt++)
                #pragma unroll
                for (int i = 0; i < 4; i++) acc[mt][nt][i] = 0.0f;
        mma_accum<KS2, S1, NP2, NT2>(buf1, sW, acc);
        epi_relu<NT2, S2>(acc, B2, buf2);
    }
    __syncthreads();

    stage_w<C2, C2, C3, NP3>(sW, W3);
    __syncthreads();

    // layer 3 + maxpool
    {
        float acc[2][NT3][4];
        #pragma unroll
        for (int mt = 0; mt < 2; mt++)
            #pragma unroll
            for (int nt = 0; nt < NT3; nt++)
                #pragma unroll
                for (int i = 0; i < 4; i++) acc[mt][nt][i] = 0.0f;
        mma_accum<KS3, S2, NP3, NT3>(buf2, sW, acc);
        epi_final<NT3, SEG>(acc, B3, sMaxI, outF, centerBase);
    }

    if (SEG == 128) {
        __syncthreads();
        for (int t = threadIdx.x; t < C3; t += NTH)
            outF[(size_t)centerBase * FEAT_W + t] = __int_as_float(sMaxI[t]);
    }
}

// =====================================================================
// host launch
// =====================================================================
template<int SEG, int C1, int C2, int C3>
static int smem_mma() {
    int S1 = C1 + 4, S2 = C2 + 4;
    int WMAX = cmax3i(72 * (C1 + 8), C1 * (C2 + 8), C2 * (C3 + 8));
    return (128 * S_IN + 128 * S1 + 128 * S2 + WMAX + 256) * 4;
}

extern "C" void kernel_launch(void* const* d_in, const int* in_sizes, int n_in,
                              void* d_out, int out_size)
{
    const float* xyz = (const float*)d_in[0];
    const float* pts = (const float*)d_in[1];
    const float* W[3][3];
    const float* Bv[3][3];
    int k = 2;
    for (int bi = 0; bi < 3; bi++)
        for (int li = 0; li < 3; li++) {
            W[bi][li]  = (const float*)d_in[k++];
            Bv[bi][li] = (const float*)d_in[k++];
        }

    float* out        = (float*)d_out;
    float* out_newxyz = out;
    float* out_feat   = out + (size_t)NCENT * 3;

    const int fps_smem = 3 * NPTS * 4;
    const int bq_smem  = 3 * NPTS * 4;
    const int sm0 = smem_mma<16, 32, 32, 64>();
    const int sm1 = smem_mma<32, 64, 64, 128>();
    const int sm2 = smem_mma<128, 64, 96, 128>();

    cudaFuncSetAttribute(fps_kernel, cudaFuncAttributeMaxDynamicSharedMemorySize, fps_smem);
    cudaFuncSetAttribute((const void*)mlp_mma_kernel<16, 32, 32, 64>,
                         cudaFuncAttributeMaxDynamicSharedMemorySize, sm0);
    cudaFuncSetAttribute((const void*)mlp_mma_kernel<32, 64, 64, 128>,
                         cudaFuncAttributeMaxDynamicSharedMemorySize, sm1);
    cudaFuncSetAttribute((const void*)mlp_mma_kernel<128, 64, 96, 128>,
                         cudaFuncAttributeMaxDynamicSharedMemorySize, sm2);

    fps_kernel<<<BATCH, 256, fps_smem>>>(xyz, out_newxyz);
    bq_fused_kernel<<<NCENT / 8, 256, bq_smem>>>(xyz, g_idx0, g_idx1, g_idx2);

    mlp_mma_kernel<128, 64, 96, 128><<<NCENT, NTH, sm2>>>(
        xyz, pts, g_idx2,
        W[2][0], Bv[2][0], W[2][1], Bv[2][1], W[2][2], Bv[2][2],
        out_feat + 192);
    mlp_mma_kernel<32, 64, 64, 128><<<NCENT / 4, NTH, sm1>>>(
        xyz, pts, g_idx1,
        W[1][0], Bv[1][0], W[1][1], Bv[1][1], W[1][2], Bv[1][2],
        out_feat + 64);
    mlp_mma_kernel<16, 32, 32, 64><<<NCENT / 8, NTH, sm0>>>(
        xyz, pts, g_idx0,
        W[0][0], Bv[0][0], W[0][1], Bv[0][1], W[0][2], Bv[0][2],
        out_feat + 0);
}

// round 6
// speedup vs baseline: 2.3129x; 1.2394x over previous
#include <cuda_runtime.h>
#include <cuda_bf16.h>
#include <cstdint>

#define BATCH   8
#define NPTS    4096
#define CIN_PTS 64
#define NPOINT  1024
#define NCENT   (BATCH * NPOINT)   // 8192
#define FEAT_W  320
#define S_IN    76                 // input stride: 67 used + zero pad
#define NTH     512                // threads per MLP block

// ---------------- device scratch ----------------
__device__ float g_new_xyz[NCENT * 3];
__device__ int   g_idx0[NCENT * 16];
__device__ int   g_idx1[NCENT * 32];
__device__ int   g_idx2[NCENT * 128];

__host__ __device__ constexpr int cmax3i(int a, int b, int c) {
    return a > b ? (a > c ? a : c) : (b > c ? b : c);
}
__host__ __device__ constexpr int cmax2i(int a, int b) { return a > b ? a : b; }

// =====================================================================
// FPS: one block per batch, 256 threads x 16 register-resident points.
// =====================================================================
__global__ __launch_bounds__(256) void fps_kernel(const float* __restrict__ xyz,
                                                  float* __restrict__ out_newxyz)
{
    int b = blockIdx.x;
    extern __shared__ float sm[];
    float* sx = sm;
    float* sy = sm + NPTS;
    float* sz = sm + 2 * NPTS;
    __shared__ unsigned long long skey[3];

    const float* base = xyz + (size_t)b * NPTS * 3;
    float px[16], py[16], pz[16], pd[16];
    #pragma unroll
    for (int r = 0; r < 16; r++) {
        int p = threadIdx.x + r * 256;
        float x = base[p * 3 + 0];
        float y = base[p * 3 + 1];
        float z = base[p * 3 + 2];
        sx[p] = x; sy[p] = y; sz[p] = z;
        px[r] = x; py[r] = y; pz[r] = z;
        pd[r] = 1e10f;
    }
    if (threadIdx.x == 0) {
        skey[0] = 0xFFFFFFFFull;   // decodes to index 0
        skey[1] = 0ull;
        skey[2] = 0ull;
    }
    __syncthreads();

    int lane = threadIdx.x & 31;

    for (int it = 0; it < NPOINT; it++) {
        int cur = it % 3, nxt = (it + 1) % 3, rst = (it + 2) % 3;
        unsigned int low = (unsigned int)skey[cur];
        int far = (int)(0xFFFFFFFFu - low);

        if (threadIdx.x == 0) {
            float fx = sx[far], fy = sy[far], fz = sz[far];
            int row = b * NPOINT + it;
            out_newxyz[row * 3 + 0] = fx;
            out_newxyz[row * 3 + 1] = fy;
            out_newxyz[row * 3 + 2] = fz;
            g_new_xyz[row * 3 + 0] = fx;
            g_new_xyz[row * 3 + 1] = fy;
            g_new_xyz[row * 3 + 2] = fz;
            skey[rst] = 0ull;
        }
        float cx = sx[far], cy = sy[far], cz = sz[far];

        float bv = -1.0f;
        int   bi = 0;
        #pragma unroll
        for (int r = 0; r < 16; r++) {
            float dx = px[r] - cx;
            float dy = py[r] - cy;
            float dz = pz[r] - cz;
            float d = __fadd_rn(__fadd_rn(__fmul_rn(dx, dx), __fmul_rn(dy, dy)),
                                __fmul_rn(dz, dz));
            float nd = fminf(pd[r], d);
            pd[r] = nd;
            if (nd > bv) { bv = nd; bi = threadIdx.x + r * 256; }
        }
        #pragma unroll
        for (int off = 16; off >= 1; off >>= 1) {
            float ov = __shfl_down_sync(0xffffffffu, bv, off);
            int   oi = __shfl_down_sync(0xffffffffu, bi, off);
            if (ov > bv || (ov == bv && oi < bi)) { bv = ov; bi = oi; }
        }
        if (lane == 0) {
            unsigned long long key =
                ((unsigned long long)__float_as_uint(bv) << 32) |
                (unsigned long long)(0xFFFFFFFFu - (unsigned int)bi);
            atomicMax(&skey[nxt], key);
        }
        __syncthreads();
    }
}

// =====================================================================
// Fused ball query (3 radii, one smem-staged scan). Warp per center.
// =====================================================================
__global__ __launch_bounds__(256) void bq_fused_kernel(const float* __restrict__ xyz,
                                                       int* __restrict__ o0,
                                                       int* __restrict__ o1,
                                                       int* __restrict__ o2)
{
    extern __shared__ float sm[];
    float* sx = sm;
    float* sy = sm + NPTS;
    float* sz = sm + 2 * NPTS;

    int wid  = threadIdx.x >> 5;
    int lane = threadIdx.x & 31;
    int gw   = blockIdx.x * 8 + wid;
    int b    = gw >> 10;

    const float* base = xyz + (size_t)b * NPTS * 3;
    for (int t = threadIdx.x; t < NPTS * 3; t += 256) {
        int p = t / 3, c = t - p * 3;
        float v = base[t];
        (c == 0 ? sx : (c == 1 ? sy : sz))[p] = v;
    }
    __syncthreads();

    const float r2_0 = (float)(0.1 * 0.1);
    const float r2_1 = (float)(0.2 * 0.2);
    const float r2_2 = (float)(0.4 * 0.4);

    float cx = g_new_xyz[gw * 3 + 0];
    float cy = g_new_xyz[gw * 3 + 1];
    float cz = g_new_xyz[gw * 3 + 2];

    int* p0 = o0 + (size_t)gw * 16;
    int* p1 = o1 + (size_t)gw * 32;
    int* p2 = o2 + (size_t)gw * 128;

    int c0 = 0, c1 = 0, c2 = 0;
    int f0 = -1, f1 = -1, f2 = -1;
    unsigned lmask = (1u << lane) - 1u;

    for (int s = 0; s < NPTS; s += 32) {
        int p = s + lane;
        float dx = sx[p] - cx;
        float dy = sy[p] - cy;
        float dz = sz[p] - cz;
        float d2 = __fadd_rn(__fadd_rn(__fmul_rn(dx, dx), __fmul_rn(dy, dy)),
                             __fmul_rn(dz, dz));
        bool h0 = d2 < r2_0, h1 = d2 < r2_1, h2 = d2 < r2_2;
        unsigned m0 = __ballot_sync(0xffffffffu, h0);
        unsigned m1 = __ballot_sync(0xffffffffu, h1);
        unsigned m2 = __ballot_sync(0xffffffffu, h2);
        if (m0) {
            if (f0 < 0) f0 = s + (__ffs(m0) - 1);
            if (h0) { int pos = c0 + __popc(m0 & lmask); if (pos < 16) p0[pos] = p; }
            c0 += __popc(m0);
        }
        if (m1) {
            if (f1 < 0) f1 = s + (__ffs(m1) - 1);
            if (h1) { int pos = c1 + __popc(m1 & lmask); if (pos < 32) p1[pos] = p; }
            c1 += __popc(m1);
        }
        if (m2) {
            if (f2 < 0) f2 = s + (__ffs(m2) - 1);
            if (h2) { int pos = c2 + __popc(m2 & lmask); if (pos < 128) p2[pos] = p; }
            c2 += __popc(m2);
        }
        if (c0 >= 16 && c1 >= 32 && c2 >= 128) break;
    }
    for (int pos = c0 + lane; pos < 16; pos += 32) p0[pos] = f0;
    for (int pos = c1 + lane; pos < 32; pos += 32) p1[pos] = f1;
    for (int pos = c2 + lane; pos < 128; pos += 32) p2[pos] = f2;
}

// =====================================================================
// tf32 mma building blocks. 512 threads: 4 m-warps (w>>2) x 4 n-warps (w&3).
// =====================================================================
__device__ __forceinline__ uint32_t f2tf32(float f) {
    uint32_t r; asm("cvt.rna.tf32.f32 %0, %1;" : "=r"(r) : "f"(f)); return r;
}

__device__ __forceinline__ void mma_tf32(float* d, const uint32_t* a, const uint32_t* b) {
    asm volatile("mma.sync.aligned.m16n8k8.row.col.f32.tf32.tf32.f32 "
                 "{%0,%1,%2,%3},{%4,%5,%6,%7},{%8,%9},{%0,%1,%2,%3};"
                 : "+f"(d[0]), "+f"(d[1]), "+f"(d[2]), "+f"(d[3])
                 : "r"(a[0]), "r"(a[1]), "r"(a[2]), "r"(a[3]),
                   "r"(b[0]), "r"(b[1]));
}

// A rows m0..m0+31 (per warp), A column offset kOff, staged W rows 0..KSTEPS*8-1.
template<int KSTEPS, int SA, int NP, int NT>
__device__ __forceinline__ void mma_accum(const float* __restrict__ sA, int kOff,
                                          const float* __restrict__ sW,
                                          float (&acc)[2][NT][4])
{
    int lane = threadIdx.x & 31;
    int w    = threadIdx.x >> 5;
    int g    = lane >> 2;
    int tg   = lane & 3;
    int m0   = (w >> 2) * 32;
    int n0   = (w & 3) * (NT * 8);

    for (int ks = 0; ks < KSTEPS; ks++) {
        int k0 = ks * 8;
        uint32_t a[2][4];
        #pragma unroll
        for (int mt = 0; mt < 2; mt++) {
            const float* Ab = sA + (m0 + 16 * mt) * SA + kOff + k0;
            a[mt][0] = f2tf32(Ab[g * SA + tg]);
            a[mt][1] = f2tf32(Ab[(g + 8) * SA + tg]);
            a[mt][2] = f2tf32(Ab[g * SA + tg + 4]);
            a[mt][3] = f2tf32(Ab[(g + 8) * SA + tg + 4]);
        }
        #pragma unroll
        for (int nt = 0; nt < NT; nt++) {
            const float* Wb = sW + k0 * NP + n0 + 8 * nt;
            uint32_t bfr[2];
            bfr[0] = f2tf32(Wb[tg * NP + g]);
            bfr[1] = f2tf32(Wb[(tg + 4) * NP + g]);
            mma_tf32(acc[0][nt], a[0], bfr);
            mma_tf32(acc[1][nt], a[1], bfr);
        }
    }
}

template<int NT, int SOUT>
__device__ __forceinline__ void epi_relu(float (&acc)[2][NT][4],
                                         const float* __restrict__ gBias,
                                         float* __restrict__ sOut)
{
    int lane = threadIdx.x & 31;
    int w    = threadIdx.x >> 5;
    int g    = lane >> 2;
    int tg   = lane & 3;
    int m0   = (w >> 2) * 32;
    int n0   = (w & 3) * (NT * 8);
    #pragma unroll
    for (int mt = 0; mt < 2; mt++)
        #pragma unroll
        for (int nt = 0; nt < NT; nt++) {
            int row = m0 + 16 * mt + g;
            int col = n0 + 8 * nt + 2 * tg;
            float b0v = gBias[col], b1v = gBias[col + 1];
            sOut[row * SOUT + col]           = fmaxf(acc[mt][nt][0] + b0v, 0.0f);
            sOut[row * SOUT + col + 1]       = fmaxf(acc[mt][nt][1] + b1v, 0.0f);
            sOut[(row + 8) * SOUT + col]     = fmaxf(acc[mt][nt][2] + b0v, 0.0f);
            sOut[(row + 8) * SOUT + col + 1] = fmaxf(acc[mt][nt][3] + b1v, 0.0f);
        }
}

template<int NT, int SEG>
__device__ __forceinline__ void epi_final(float (&acc)[2][NT][4],
                                          const float* __restrict__ gBias,
                                          int* __restrict__ sMaxI,
                                          float* __restrict__ outF, int centerBase)
{
    int lane = threadIdx.x & 31;
    int w    = threadIdx.x >> 5;
    int g    = lane >> 2;
    int tg   = lane & 3;
    int n0   = (w & 3) * (NT * 8);

    if (SEG == 128) {
        #pragma unroll
        for (int nt = 0; nt < NT; nt++) {
            int col = n0 + 8 * nt + 2 * tg;
            float v0 = fmaxf(fmaxf(acc[0][nt][0], acc[0][nt][2]),
                             fmaxf(acc[1][nt][0], acc[1][nt][2]));
            float v1 = fmaxf(fmaxf(acc[0][nt][1], acc[0][nt][3]),
                             fmaxf(acc[1][nt][1], acc[1][nt][3]));
            v0 = fmaxf(v0 + gBias[col], 0.0f);
            v1 = fmaxf(v1 + gBias[col + 1], 0.0f);
            #pragma unroll
            for (int off = 4; off < 32; off <<= 1) {
                v0 = fmaxf(v0, __shfl_xor_sync(0xffffffffu, v0, off));
                v1 = fmaxf(v1, __shfl_xor_sync(0xffffffffu, v1, off));
            }
            if (g == 0) {
                atomicMax(&sMaxI[col],     __float_as_int(v0));
                atomicMax(&sMaxI[col + 1], __float_as_int(v1));
            }
        }
    } else if (SEG == 32) {
        int center = centerBase + (w >> 2);
        #pragma unroll
        for (int nt = 0; nt < NT; nt++) {
            int col = n0 + 8 * nt + 2 * tg;
            float v0 = fmaxf(fmaxf(acc[0][nt][0], acc[0][nt][2]),
                             fmaxf(acc[1][nt][0], acc[1][nt][2]));
            float v1 = fmaxf(fmaxf(acc[0][nt][1], acc[0][nt][3]),
                             fmaxf(acc[1][nt][1], acc[1][nt][3]));
            #pragma unroll
            for (int off = 4; off < 32; off <<= 1) {
                v0 = fmaxf(v0, __shfl_xor_sync(0xffffffffu, v0, off));
                v1 = fmaxf(v1, __shfl_xor_sync(0xffffffffu, v1, off));
            }
            if (g == 0) {
                float* op = outF + (size_t)center * FEAT_W;
                op[col]     = fmaxf(v0 + gBias[col], 0.0f);
                op[col + 1] = fmaxf(v1 + gBias[col + 1], 0.0f);
            }
        }
    } else { // SEG == 16: each m-tile (mt) is one center
        #pragma unroll
        for (int mt = 0; mt < 2; mt++) {
            int center = centerBase + (w >> 2) * 2 + mt;
            #pragma unroll
            for (int nt = 0; nt < NT; nt++) {
                int col = n0 + 8 * nt + 2 * tg;
                float v0 = fmaxf(acc[mt][nt][0], acc[mt][nt][2]);
                float v1 = fmaxf(acc[mt][nt][1], acc[mt][nt][3]);
                #pragma unroll
                for (int off = 4; off < 32; off <<= 1) {
                    v0 = fmaxf(v0, __shfl_xor_sync(0xffffffffu, v0, off));
                    v1 = fmaxf(v1, __shfl_xor_sync(0xffffffffu, v1, off));
                }
                if (g == 0) {
                    float* op = outF + (size_t)center * FEAT_W;
                    op[col]     = fmaxf(v0 + gBias[col], 0.0f);
                    op[col + 1] = fmaxf(v1 + gBias[col + 1], 0.0f);
                }
            }
        }
    }
}

template<int ROWS, int KR, int NC, int NP>
__device__ __forceinline__ void stage_w(float* __restrict__ sW, const float* __restrict__ gW)
{
    for (int t = threadIdx.x; t < ROWS * NP; t += NTH) {
        int r = t / NP, c = t - r * NP;
        sW[t] = (r < KR && c < NC) ? gW[r * NC + c] : 0.0f;
    }
}

// =====================================================================
// Unified MLP kernel (512 threads). One block = 128 rows.
// buf2 aliases sIn (dead after layer 1). W3 staged in chunks for C2==96.
// =====================================================================
template<int SEG, int C1, int C2, int C3>
__global__ __launch_bounds__(NTH) void mlp_mma_kernel(const float* __restrict__ xyz,
                                                      const float* __restrict__ points,
                                                      const int* __restrict__ idxbuf,
                                                      const float* __restrict__ W1, const float* __restrict__ B1,
                                                      const float* __restrict__ W2, const float* __restrict__ B2,
                                                      const float* __restrict__ W3, const float* __restrict__ B3,
                                                      float* __restrict__ outF)
{
    constexpr int CPB  = 128 / SEG;
    constexpr int S1   = C1 + 4, S2 = C2 + 4;
    constexpr int NP1  = C1 + 8, NP2 = C2 + 8, NP3 = C3 + 8;
    constexpr int W3CH = (C2 == 96) ? 48 : C2;   // W3 staging chunk rows
    constexpr int NCH  = C2 / W3CH;
    constexpr int REG0 = 128 * cmax2i(S_IN, S2); // sIn region, reused as buf2
    constexpr int WMAX = cmax3i(72 * NP1, C1 * NP2, W3CH * NP3);
    constexpr int KS2  = C1 / 8;
    constexpr int NT1  = C1 / 32, NT2 = C2 / 32, NT3 = C3 / 32;

    extern __shared__ float sm[];
    float* sIn   = sm;                  // [REG0] (later reused as buf2)
    float* buf1  = sm + REG0;           // 128 * S1
    float* sW    = buf1 + 128 * S1;     // WMAX
    int*   sMaxI = (int*)(sW + WMAX);   // 128
    int*   sIdx  = sMaxI + 128;         // 128

    int centerBase = blockIdx.x * CPB;
    int b = centerBase >> 10;

    for (int t = threadIdx.x; t < 128; t += NTH) {
        sIdx[t]  = idxbuf[(size_t)centerBase * SEG + t];
        sMaxI[t] = 0;
    }
    __syncthreads();

    const float* pB = points + (size_t)b * NPTS * CIN_PTS;
    const float* xB = xyz + (size_t)b * NPTS * 3;

    for (int t = threadIdx.x; t < 128 * S_IN; t += NTH) {
        int s = t / S_IN, c = t - s * S_IN;
        int ci = centerBase + s / SEG;
        float v;
        if (c < 64)       v = pB[(size_t)sIdx[s] * CIN_PTS + c];
        else if (c < 67) {
            int d = c - 64;
            v = xB[(size_t)sIdx[s] * 3 + d] - g_new_xyz[ci * 3 + d];
        } else v = 0.0f;
        sIn[t] = v;
    }
    stage_w<72, 67, C1, NP1>(sW, W1);
    __syncthreads();

    // layer 1: sIn -> buf1
    {
        float acc[2][NT1][4];
        #pragma unroll
        for (int mt = 0; mt < 2; mt++)
            #pragma unroll
            for (int nt = 0; nt < NT1; nt++)
                #pragma unroll
                for (int i = 0; i < 4; i++) acc[mt][nt][i] = 0.0f;
        mma_accum<9, S_IN, NP1, NT1>(sIn, 0, sW, acc);
        epi_relu<NT1, S1>(acc, B1, buf1);
    }
    __syncthreads();

    stage_w<C1, C1, C2, NP2>(sW, W2);
    __syncthreads();

    // layer 2: buf1 -> buf2 (aliases sIn; sIn fully consumed in layer 1)
    float* buf2 = sIn;
    {
        float acc[2][NT2][4];
        #pragma unroll
        for (int mt = 0; mt < 2; mt++)
            #pragma unroll
            for (int nt = 0; nt < NT2; nt++)
                #pragma unroll
                for (int i = 0; i < 4; i++) acc[mt][nt][i] = 0.0f;
        mma_accum<KS2, S1, NP2, NT2>(buf1, 0, sW, acc);
        epi_relu<NT2, S2>(acc, B2, buf2);
    }
    __syncthreads();

    // layer 3: buf2 -> maxpool output. W3 staged in NCH chunks of W3CH rows.
    {
        float acc[2][NT3][4];
        #pragma unroll
        for (int mt = 0; mt < 2; mt++)
            #pragma unroll
            for (int nt = 0; nt < NT3; nt++)
                #pragma unroll
                for (int i = 0; i < 4; i++) acc[mt][nt][i] = 0.0f;
        for (int ch = 0; ch < NCH; ch++) {
            stage_w<W3CH, W3CH, C3, NP3>(sW, W3 + (size_t)ch * W3CH * C3);
            __syncthreads();
            mma_accum<W3CH / 8, S2, NP3, NT3>(buf2, ch * W3CH, sW, acc);
            __syncthreads();
        }
        epi_final<NT3, SEG>(acc, B3, sMaxI, outF, centerBase);
    }

    if (SEG == 128) {
        __syncthreads();
        for (int t = threadIdx.x; t < C3; t += NTH)
            outF[(size_t)centerBase * FEAT_W + t] = __int_as_float(sMaxI[t]);
    }
}

// =====================================================================
// host launch
// =====================================================================
template<int SEG, int C1, int C2, int C3>
static constexpr int smem_mma() {
    constexpr int S2 = C2 + 4;
    constexpr int W3CH = (C2 == 96) ? 48 : C2;
    constexpr int WMAX = cmax3i(72 * (C1 + 8), C1 * (C2 + 8), W3CH * (C3 + 8));
    constexpr int REG0 = 128 * cmax2i(S_IN, S2);
    return (REG0 + 128 * (C1 + 4) + WMAX + 256) * 4;
}

extern "C" void kernel_launch(void* const* d_in, const int* in_sizes, int n_in,
                              void* d_out, int out_size)
{
    const float* xyz = (const float*)d_in[0];
    const float* pts = (const float*)d_in[1];
    const float* W[3][3];
    const float* Bv[3][3];
    int k = 2;
    for (int bi = 0; bi < 3; bi++)
        for (int li = 0; li < 3; li++) {
            W[bi][li]  = (const float*)d_in[k++];
            Bv[bi][li] = (const float*)d_in[k++];
        }

    float* out        = (float*)d_out;
    float* out_newxyz = out;
    float* out_feat   = out + (size_t)NCENT * 3;

    const int fps_smem = 3 * NPTS * 4;
    const int bq_smem  = 3 * NPTS * 4;
    constexpr int sm0 = smem_mma<16, 32, 32, 64>();     //  69,888 B -> 3 blocks/SM
    constexpr int sm1 = smem_mma<32, 64, 64, 128>();    // 109,568 B -> 2 blocks/SM
    constexpr int sm2 = smem_mma<128, 64, 96, 128>();   // 113,664 B -> 2 blocks/SM

    cudaFuncSetAttribute(fps_kernel, cudaFuncAttributeMaxDynamicSharedMemorySize, fps_smem);
    cudaFuncSetAttribute((const void*)mlp_mma_kernel<16, 32, 32, 64>,
                         cudaFuncAttributeMaxDynamicSharedMemorySize, sm0);
    cudaFuncSetAttribute((const void*)mlp_mma_kernel<32, 64, 64, 128>,
                         cudaFuncAttributeMaxDynamicSharedMemorySize, sm1);
    cudaFuncSetAttribute((const void*)mlp_mma_kernel<128, 64, 96, 128>,
                         cudaFuncAttributeMaxDynamicSharedMemorySize, sm2);

    fps_kernel<<<BATCH, 256, fps_smem>>>(xyz, out_newxyz);
    bq_fused_kernel<<<NCENT / 8, 256, bq_smem>>>(xyz, g_idx0, g_idx1, g_idx2);

    mlp_mma_kernel<128, 64, 96, 128><<<NCENT, NTH, sm2>>>(
        xyz, pts, g_idx2,
        W[2][0], Bv[2][0], W[2][1], Bv[2][1], W[2][2], Bv[2][2],
        out_feat + 192);
    mlp_mma_kernel<32, 64, 64, 128><<<NCENT / 4, NTH, sm1>>>(
        xyz, pts, g_idx1,
        W[1][0], Bv[1][0], W[1][1], Bv[1][1], W[1][2], Bv[1][2],
        out_feat + 64);
    mlp_mma_kernel<16, 32, 32, 64><<<NCENT / 8, NTH, sm0>>>(
        xyz, pts, g_idx0,
        W[0][0], Bv[0][0], W[0][1], Bv[0][1], W[0][2], Bv[0][2],
        out_feat + 0);
}